// round 4
// baseline (speedup 1.0000x reference)
#include <cuda_runtime.h>
#include <math.h>
#include <stdint.h>

// ===========================================================================
// img_attention via warp-level TF32 mma.sync (compute_103-safe)
//   c_img = softmax(v . tanh(Wh g* + Ws s + Wc cov)) @ g*
//   g*    = X @ (W_g @ W_gs) + (b_g @ W_gs + b_gs)      [algebraic fold]
// GEMMs: D[m,n] = sum_k A[m,k] * Bt[n,k]  (both K-major)
// R4: 64x64 warp tiles (128-thr CTAs, no spills), scores fused into the
//     e_pre GEMM epilogue (epre never materialized), hw tanh.approx.
// ===========================================================================

#define B_   128
#define N_   49
#define G_   4096
#define H_   1024
#define A_   1024
#define BN_  (B_ * N_)   // 6272

__device__ float g_WcombT[H_ * G_];     // [1024,4096] = (W_g @ W_gs)^T
__device__ float g_biascomb[H_];
__device__ float g_gstar[BN_ * H_];     // [6272,1024]
__device__ float g_scratch[BN_ * A_];   // holds WgsT [1024,4096]
__device__ float g_WhT[A_ * H_];
__device__ float g_WsT[A_ * H_];
__device__ float g_sproj[B_ * A_];
__device__ float g_scores[BN_];

// ---------------------------------------------------------------------------
__device__ __forceinline__ uint32_t smem_u32(const void* p) {
    uint32_t a;
    asm("{ .reg .u64 t; cvta.to.shared.u64 t, %1; cvt.u32.u64 %0, t; }"
        : "=r"(a) : "l"(p));
    return a;
}
__device__ __forceinline__ float to_tf32(float x) {
    uint32_t u;
    asm("cvt.rna.tf32.f32 %0, %1;" : "=r"(u) : "f"(x));
    return __uint_as_float(u);
}
__device__ __forceinline__ float tanh_approx(float x) {
    float y;
    asm("tanh.approx.f32 %0, %1;" : "=f"(y) : "f"(x));
    return y;
}
__device__ __forceinline__ void ldsm4(uint32_t* r, uint32_t addr) {
    asm volatile("ldmatrix.sync.aligned.m8n8.x4.shared.b16 {%0,%1,%2,%3}, [%4];"
                 : "=r"(r[0]), "=r"(r[1]), "=r"(r[2]), "=r"(r[3]) : "r"(addr));
}
__device__ __forceinline__ void mma_tf32(float* d, const uint32_t* a,
                                         const uint32_t* b) {
    asm volatile(
        "mma.sync.aligned.m16n8k8.row.col.f32.tf32.tf32.f32 "
        "{%0,%1,%2,%3}, {%4,%5,%6,%7}, {%8,%9}, {%0,%1,%2,%3};"
        : "+f"(d[0]), "+f"(d[1]), "+f"(d[2]), "+f"(d[3])
        : "r"(a[0]), "r"(a[1]), "r"(a[2]), "r"(a[3]), "r"(b[0]), "r"(b[1]));
}

// ---------------------------------------------------------------------------
// Shared GEMM machinery: 128x128 block, BK=32, 128 threads, 2x2 warps of
// 64x64. Double-buffered smem: 2 stages x (16KB A + 16KB B) = 64KB.
// ---------------------------------------------------------------------------
#define TCSM (2 * 32768)

// staging: each thread loads 8 float4 per operand
#define GEMM_PROLOG()                                                         \
    extern __shared__ char smem[];                                            \
    const uint32_t sb = smem_u32(smem);                                       \
    const int tid = threadIdx.x;                                              \
    const int lane = tid & 31;                                                \
    const int wid = tid >> 5;                                                 \
    const int wr = wid >> 1;   /* 0..1 */                                     \
    const int wc = wid & 1;    /* 0..1 */                                     \
    const int srow = tid >> 3, sc4 = tid & 7;                                 \
    const uint32_t soff0 = (uint32_t)srow * 128 + ((sc4 ^ (srow & 7)) << 4);  \
    const int aRow = wr * 64 + ((lane >> 3) & 1) * 8 + (lane & 7);            \
    const int cbA = lane >> 4;                                                \
    const uint32_t aBase = (uint32_t)aRow * 128;                              \
    const int rmA = aRow & 7;                                                 \
    const int bRow = wc * 64 + (lane >> 4) * 8 + (lane & 7);                  \
    const int cbB = (lane >> 3) & 1;                                          \
    const uint32_t bBase = (uint32_t)bRow * 128;                              \
    const int rmB = bRow & 7;                                                 \
    float acc[4][8][4];                                                       \
    _Pragma("unroll") for (int i = 0; i < 4; i++)                             \
        _Pragma("unroll") for (int j = 0; j < 8; j++)                         \
            _Pragma("unroll") for (int q = 0; q < 4; q++) acc[i][j][q] = 0.f; \
    float4 sa[8], sbv[8];

#define LOADG(k0) {                                                           \
    _Pragma("unroll") for (int j = 0; j < 8; j++) {                           \
        sa[j]  = *(const float4*)(pA0 + j * strideJ + (k0));                  \
        sbv[j] = *(const float4*)(pB0 + j * strideJ + (k0));                  \
    } }

#define STST(stoff) {                                                         \
    _Pragma("unroll") for (int j = 0; j < 8; j++) {                           \
        float4 v4 = sa[j];                                                    \
        v4.x = to_tf32(v4.x); v4.y = to_tf32(v4.y);                           \
        v4.z = to_tf32(v4.z); v4.w = to_tf32(v4.w);                           \
        *(float4*)(smem + (stoff) + soff0 + j * 2048) = v4;                   \
        float4 w4 = sbv[j];                                                   \
        w4.x = to_tf32(w4.x); w4.y = to_tf32(w4.y);                           \
        w4.z = to_tf32(w4.z); w4.w = to_tf32(w4.w);                           \
        *(float4*)(smem + (stoff) + 16384 + soff0 + j * 2048) = w4;           \
    } }

#define COMPUTE_CHUNK(As, Bs) {                                               \
    _Pragma("unroll") for (int kc = 0; kc < 4; kc++) {                        \
        uint32_t afr[4][4], bfr[8][2];                                        \
        _Pragma("unroll") for (int fm = 0; fm < 4; fm++)                      \
            ldsm4(afr[fm],                                                    \
                  (As) + fm * 2048 + aBase + ((((kc * 2) + cbA) ^ rmA) << 4));\
        _Pragma("unroll") for (int p = 0; p < 4; p++) {                       \
            uint32_t t4[4];                                                   \
            ldsm4(t4,                                                         \
                  (Bs) + p * 2048 + bBase + ((((kc * 2) + cbB) ^ rmB) << 4)); \
            bfr[2*p][0]   = t4[0]; bfr[2*p][1]   = t4[1];                     \
            bfr[2*p+1][0] = t4[2]; bfr[2*p+1][1] = t4[3];                     \
        }                                                                     \
        _Pragma("unroll") for (int fm = 0; fm < 4; fm++)                      \
            _Pragma("unroll") for (int fn = 0; fn < 8; fn++)                  \
                mma_tf32(acc[fm][fn], afr[fm], bfr[fn]);                      \
    } }

#define MAINLOOP(nch)                                                         \
    LOADG(0);                                                                 \
    STST(0);                                                                  \
    for (int c = 0; c < (nch); c++) {                                         \
        if (c + 1 < (nch)) LOADG((c + 1) * 32);                               \
        __syncthreads();                                                      \
        if (c + 1 < (nch)) STST(((c + 1) & 1) * 32768);                       \
        COMPUTE_CHUNK(sb + (c & 1) * 32768, sb + (c & 1) * 32768 + 16384);    \
    }

// ---------------------------------------------------------------------------
// Generic GEMM: D[M,Nn] = A @ Bt^T (+ bias). M%128==0, Nn%128==0, K%64==0.
// ---------------------------------------------------------------------------
__global__ __launch_bounds__(128, 2)
void mma_gemm(const float* __restrict__ A, const float* __restrict__ Bt,
              const float* __restrict__ bias, float* __restrict__ C,
              int M, int Nn, int K)
{
    const int bm = blockIdx.y * 128;
    const int bn = blockIdx.x * 128;
    GEMM_PROLOG();
    const float* pA0 = A  + (size_t)(bm + srow) * K + sc4 * 4;
    const float* pB0 = Bt + (size_t)(bn + srow) * K + sc4 * 4;
    const size_t strideJ = (size_t)16 * K;
    const int nch = K >> 5;
    MAINLOOP(nch);

    const int gid = lane >> 2, tig = lane & 3;
    #pragma unroll
    for (int fm = 0; fm < 4; fm++) {
        const int row = bm + wr * 64 + fm * 16 + gid;
        #pragma unroll
        for (int fn = 0; fn < 8; fn++) {
            const int col = bn + wc * 64 + fn * 8 + tig * 2;
            float b0 = 0.f, b1 = 0.f;
            if (bias != nullptr) { b0 = bias[col]; b1 = bias[col + 1]; }
            float2 v01, v23;
            v01.x = acc[fm][fn][0] + b0; v01.y = acc[fm][fn][1] + b1;
            v23.x = acc[fm][fn][2] + b0; v23.y = acc[fm][fn][3] + b1;
            *(float2*)(C + (size_t)row * Nn + col) = v01;
            *(float2*)(C + (size_t)(row + 8) * Nn + col) = v23;
        }
    }
}

// ---------------------------------------------------------------------------
// Fused e_pre GEMM + scores epilogue.  acc = gstar @ WhT^T  (K=1024), then
// scores[row] += sum_col v[col]*tanh(acc + sproj[b,col] + cov[row]*Wc[col])
// Nothing stored to gmem except score atomics.
// ---------------------------------------------------------------------------
__global__ __launch_bounds__(128, 2)
void epre_scores_gemm(const float* __restrict__ A, const float* __restrict__ Bt,
                      const float* __restrict__ sproj,
                      const float* __restrict__ cov,
                      const float* __restrict__ Wc,
                      const float* __restrict__ v,
                      float* __restrict__ scores)
{
    const int bm = blockIdx.y * 128;
    const int bn = blockIdx.x * 128;
    GEMM_PROLOG();
    const float* pA0 = A  + (size_t)(bm + srow) * H_ + sc4 * 4;
    const float* pB0 = Bt + (size_t)(bn + srow) * H_ + sc4 * 4;
    const size_t strideJ = (size_t)16 * H_;
    MAINLOOP(H_ / 32);

    // epilogue: v, Wc per column (16 cols per thread), cov per row, sproj[b,col]
    const int gid = lane >> 2, tig = lane & 3;
    float vv[16], wcv[16];
    #pragma unroll
    for (int fn = 0; fn < 8; fn++) {
        const int col = bn + wc * 64 + fn * 8 + tig * 2;
        vv[2*fn]   = v[col];      vv[2*fn+1]  = v[col + 1];
        wcv[2*fn]  = Wc[col];     wcv[2*fn+1] = Wc[col + 1];
    }
    #pragma unroll
    for (int fm = 0; fm < 4; fm++) {
        const int r0 = bm + wr * 64 + fm * 16 + gid;
        const int r1 = r0 + 8;
        const int b0i = r0 / N_, b1i = r1 / N_;
        const float c0 = cov[r0], c1 = cov[r1];
        const float* sp0 = sproj + (size_t)b0i * A_;
        const float* sp1 = sproj + (size_t)b1i * A_;
        float p0 = 0.f, p1 = 0.f;
        #pragma unroll
        for (int fn = 0; fn < 8; fn++) {
            const int col = bn + wc * 64 + fn * 8 + tig * 2;
            p0 += vv[2*fn]   * tanh_approx(acc[fm][fn][0] + sp0[col]     + c0 * wcv[2*fn]);
            p0 += vv[2*fn+1] * tanh_approx(acc[fm][fn][1] + sp0[col + 1] + c0 * wcv[2*fn+1]);
            p1 += vv[2*fn]   * tanh_approx(acc[fm][fn][2] + sp1[col]     + c1 * wcv[2*fn]);
            p1 += vv[2*fn+1] * tanh_approx(acc[fm][fn][3] + sp1[col + 1] + c1 * wcv[2*fn+1]);
        }
        p0 += __shfl_xor_sync(0xffffffffu, p0, 1);
        p0 += __shfl_xor_sync(0xffffffffu, p0, 2);
        p1 += __shfl_xor_sync(0xffffffffu, p1, 1);
        p1 += __shfl_xor_sync(0xffffffffu, p1, 2);
        if (tig == 0) {
            atomicAdd(scores + r0, p0);
            atomicAdd(scores + r1, p1);
        }
    }
}

// ---------------------------------------------------------------------------
__global__ __launch_bounds__(256) void transpose_kernel(
    const float* __restrict__ in, float* __restrict__ out, int R, int C)
{
    __shared__ float t[32][33];
    const int c0 = blockIdx.x * 32, r0 = blockIdx.y * 32;
    const int x = threadIdx.x, y = threadIdx.y;
    #pragma unroll
    for (int j = 0; j < 32; j += 8)
        t[y + j][x] = in[(size_t)(r0 + y + j) * C + c0 + x];
    __syncthreads();
    #pragma unroll
    for (int j = 0; j < 32; j += 8)
        out[(size_t)(c0 + y + j) * R + r0 + x] = t[x][y + j];
}

__global__ void bias_init_kernel(const float* __restrict__ b_gs,
                                 float* __restrict__ bias) {
    int h = blockIdx.x * blockDim.x + threadIdx.x;
    if (h < H_) bias[h] = b_gs[h];
}
__global__ void bias_acc_kernel(const float* __restrict__ b_g,
                                const float* __restrict__ W_gs,
                                float* __restrict__ bias) {
    int h = blockIdx.x * blockDim.x + threadIdx.x;
    int k0 = blockIdx.y * 256;
    float acc = 0.f;
    #pragma unroll 4
    for (int k = k0; k < k0 + 256; k++)
        acc += b_g[k] * W_gs[(size_t)k * H_ + h];
    atomicAdd(&bias[h], acc);
}

__global__ void zero_scores_kernel(float* __restrict__ scores) {
    int i = blockIdx.x * blockDim.x + threadIdx.x;
    if (i < BN_) scores[i] = 0.f;
}

// softmax over N=49 + context c[b,h] = sum_n alpha[n] * gstar[b,n,h]
__global__ __launch_bounds__(256) void context_kernel(
    const float* __restrict__ scores, const float* __restrict__ gstar,
    float* __restrict__ out)
{
    const int b = blockIdx.x;
    __shared__ float alpha[N_];
    const int tid = threadIdx.x;

    if (tid == 0) {
        float m = -1e30f;
        #pragma unroll
        for (int n = 0; n < N_; n++) m = fmaxf(m, scores[b * N_ + n]);
        float s = 0.f;
        #pragma unroll
        for (int n = 0; n < N_; n++) {
            float e = expf(scores[b * N_ + n] - m);
            alpha[n] = e;
            s += e;
        }
        float inv = 1.f / s;
        #pragma unroll
        for (int n = 0; n < N_; n++) alpha[n] *= inv;
    }
    __syncthreads();

    const float* gb = gstar + (size_t)b * N_ * H_;
    for (int h = tid; h < H_; h += 256) {
        float acc = 0.f;
        #pragma unroll
        for (int n = 0; n < N_; n++)
            acc += alpha[n] * gb[(size_t)n * H_ + h];
        out[(size_t)b * H_ + h] = acc;
    }
}

// ---------------------------------------------------------------------------
extern "C" void kernel_launch(void* const* d_in, const int* in_sizes, int n_in,
                              void* d_out, int out_size) {
    const float* X    = (const float*)d_in[0];   // [6272,4096]
    const float* s_t  = (const float*)d_in[1];   // [128,1024]
    const float* cov  = (const float*)d_in[2];   // [6272]
    const float* W_g  = (const float*)d_in[3];   // [4096,4096]
    const float* b_g  = (const float*)d_in[4];   // [4096]
    const float* W_gs = (const float*)d_in[5];   // [4096,1024]
    const float* b_gs = (const float*)d_in[6];   // [1024]
    const float* W_h  = (const float*)d_in[7];   // [1024,1024]
    const float* W_s  = (const float*)d_in[8];   // [1024,1024]
    const float* W_c  = (const float*)d_in[9];   // [1024]
    const float* v    = (const float*)d_in[10];  // [1024]
    float* out = (float*)d_out;                  // [128,1024]

    float *WcombT, *biascomb, *gstar, *scratch, *WhT, *WsT, *sproj, *scores;
    cudaGetSymbolAddress((void**)&WcombT,   g_WcombT);
    cudaGetSymbolAddress((void**)&biascomb, g_biascomb);
    cudaGetSymbolAddress((void**)&gstar,    g_gstar);
    cudaGetSymbolAddress((void**)&scratch,  g_scratch);
    cudaGetSymbolAddress((void**)&WhT,      g_WhT);
    cudaGetSymbolAddress((void**)&WsT,      g_WsT);
    cudaGetSymbolAddress((void**)&sproj,    g_sproj);
    cudaGetSymbolAddress((void**)&scores,   g_scores);

    cudaFuncSetAttribute(mma_gemm,
                         cudaFuncAttributeMaxDynamicSharedMemorySize, TCSM);
    cudaFuncSetAttribute(epre_scores_gemm,
                         cudaFuncAttributeMaxDynamicSharedMemorySize, TCSM);

    float* WgsT = scratch;   // [1024,4096]

    dim3 tb(32, 8);
    transpose_kernel<<<dim3(H_ / 32, G_ / 32), tb>>>(W_gs, WgsT, G_, H_);
    transpose_kernel<<<dim3(A_ / 32, H_ / 32), tb>>>(W_h, WhT, H_, A_);
    transpose_kernel<<<dim3(A_ / 32, H_ / 32), tb>>>(W_s, WsT, H_, A_);

    bias_init_kernel<<<H_ / 256, 256>>>(b_gs, biascomb);
    bias_acc_kernel<<<dim3(H_ / 256, G_ / 256), 256>>>(b_g, W_gs, biascomb);
    zero_scores_kernel<<<(BN_ + 255) / 256, 256>>>(scores);

    // WcombT[h,g] = sum_k WgsT[h,k] * W_g[g,k]   (M=1024, N=4096, K=4096)
    mma_gemm<<<dim3(G_ / 128, H_ / 128), 128, TCSM>>>(
        WgsT, W_g, nullptr, WcombT, H_, G_, G_);

    // g_star[m,h] = sum_k X[m,k] * WcombT[h,k] + bias[h]
    mma_gemm<<<dim3(H_ / 128, BN_ / 128), 128, TCSM>>>(
        X, WcombT, biascomb, gstar, BN_, H_, G_);

    // s_proj[b,a] = sum_h s_t[b,h] * WsT[a,h]
    mma_gemm<<<dim3(A_ / 128, B_ / 128), 128, TCSM>>>(
        s_t, WsT, nullptr, sproj, B_, A_, H_);

    // fused: e_pre + tanh + v-dot -> scores (epre never materialized)
    epre_scores_gemm<<<dim3(A_ / 128, BN_ / 128), 128, TCSM>>>(
        gstar, WhT, sproj, cov, W_c, v, scores);

    context_kernel<<<B_, 256>>>(scores, gstar, out);
}

// round 5
// speedup vs baseline: 1.2937x; 1.2937x over previous
#include <cuda_runtime.h>
#include <math.h>
#include <stdint.h>

// ===========================================================================
// img_attention via warp-level TF32 mma.sync (compute_103-safe)
//   c_img = softmax(v . tanh(Wh g* + Ws s + Wc cov)) @ g*
//   g*    = X @ (W_g @ W_gs) + (b_g @ W_gs + b_gs)      [algebraic fold]
// GEMMs: D[m,n] = sum_k A[m,k] * Bt[n,k]  (both K-major)
// R5: pipeline order fixed (LDG in flight DURING compute, not before),
//     split-K sproj. Fused scores epilogue kept from R4.
// ===========================================================================

#define B_   128
#define N_   49
#define G_   4096
#define H_   1024
#define A_   1024
#define BN_  (B_ * N_)   // 6272

__device__ float g_WcombT[H_ * G_];     // [1024,4096] = (W_g @ W_gs)^T
__device__ float g_biascomb[H_];
__device__ float g_gstar[BN_ * H_];     // [6272,1024]
__device__ float g_scratch[BN_ * A_];   // holds WgsT [1024,4096]
__device__ float g_WhT[A_ * H_];
__device__ float g_WsT[A_ * H_];
__device__ float g_sproj[B_ * A_];
__device__ float g_scores[BN_];

// ---------------------------------------------------------------------------
__device__ __forceinline__ uint32_t smem_u32(const void* p) {
    uint32_t a;
    asm("{ .reg .u64 t; cvta.to.shared.u64 t, %1; cvt.u32.u64 %0, t; }"
        : "=r"(a) : "l"(p));
    return a;
}
__device__ __forceinline__ float to_tf32(float x) {
    uint32_t u;
    asm("cvt.rna.tf32.f32 %0, %1;" : "=r"(u) : "f"(x));
    return __uint_as_float(u);
}
__device__ __forceinline__ float tanh_approx(float x) {
    float y;
    asm("tanh.approx.f32 %0, %1;" : "=f"(y) : "f"(x));
    return y;
}
__device__ __forceinline__ void ldsm4(uint32_t* r, uint32_t addr) {
    asm volatile("ldmatrix.sync.aligned.m8n8.x4.shared.b16 {%0,%1,%2,%3}, [%4];"
                 : "=r"(r[0]), "=r"(r[1]), "=r"(r[2]), "=r"(r[3]) : "r"(addr));
}
__device__ __forceinline__ void mma_tf32(float* d, const uint32_t* a,
                                         const uint32_t* b) {
    asm volatile(
        "mma.sync.aligned.m16n8k8.row.col.f32.tf32.tf32.f32 "
        "{%0,%1,%2,%3}, {%4,%5,%6,%7}, {%8,%9}, {%0,%1,%2,%3};"
        : "+f"(d[0]), "+f"(d[1]), "+f"(d[2]), "+f"(d[3])
        : "r"(a[0]), "r"(a[1]), "r"(a[2]), "r"(a[3]), "r"(b[0]), "r"(b[1]));
}

// ---------------------------------------------------------------------------
// GEMM machinery: 128x128 block, BK=32, 128 threads, 2x2 warps of 64x64.
// Double-buffered smem: 2 stages x (16KB A + 16KB B) = 64KB.
// ---------------------------------------------------------------------------
#define TCSM (2 * 32768)

#define GEMM_PROLOG()                                                         \
    extern __shared__ char smem[];                                            \
    const uint32_t sb = smem_u32(smem);                                       \
    const int tid = threadIdx.x;                                              \
    const int lane = tid & 31;                                                \
    const int wid = tid >> 5;                                                 \
    const int wr = wid >> 1;   /* 0..1 */                                     \
    const int wc = wid & 1;    /* 0..1 */                                     \
    const int srow = tid >> 3, sc4 = tid & 7;                                 \
    const uint32_t soff0 = (uint32_t)srow * 128 + ((sc4 ^ (srow & 7)) << 4);  \
    const int aRow = wr * 64 + ((lane >> 3) & 1) * 8 + (lane & 7);            \
    const int cbA = lane >> 4;                                                \
    const uint32_t aBase = (uint32_t)aRow * 128;                              \
    const int rmA = aRow & 7;                                                 \
    const int bRow = wc * 64 + (lane >> 4) * 8 + (lane & 7);                  \
    const int cbB = (lane >> 3) & 1;                                          \
    const uint32_t bBase = (uint32_t)bRow * 128;                              \
    const int rmB = bRow & 7;                                                 \
    float acc[4][8][4];                                                       \
    _Pragma("unroll") for (int i = 0; i < 4; i++)                             \
        _Pragma("unroll") for (int j = 0; j < 8; j++)                         \
            _Pragma("unroll") for (int q = 0; q < 4; q++) acc[i][j][q] = 0.f; \
    float4 sa[8], sbv[8];

#define LOADG(k0) {                                                           \
    _Pragma("unroll") for (int j = 0; j < 8; j++) {                           \
        sa[j]  = *(const float4*)(pA0 + j * strideJ + (k0));                  \
        sbv[j] = *(const float4*)(pB0 + j * strideJ + (k0));                  \
    } }

#define STST(stoff) {                                                         \
    _Pragma("unroll") for (int j = 0; j < 8; j++) {                           \
        float4 v4 = sa[j];                                                    \
        v4.x = to_tf32(v4.x); v4.y = to_tf32(v4.y);                           \
        v4.z = to_tf32(v4.z); v4.w = to_tf32(v4.w);                           \
        *(float4*)(smem + (stoff) + soff0 + j * 2048) = v4;                   \
        float4 w4 = sbv[j];                                                   \
        w4.x = to_tf32(w4.x); w4.y = to_tf32(w4.y);                           \
        w4.z = to_tf32(w4.z); w4.w = to_tf32(w4.w);                           \
        *(float4*)(smem + (stoff) + 16384 + soff0 + j * 2048) = w4;           \
    } }

#define COMPUTE_CHUNK(As, Bs) {                                               \
    _Pragma("unroll") for (int kc = 0; kc < 4; kc++) {                        \
        uint32_t afr[4][4], bfr[8][2];                                        \
        _Pragma("unroll") for (int fm = 0; fm < 4; fm++)                      \
            ldsm4(afr[fm],                                                    \
                  (As) + fm * 2048 + aBase + ((((kc * 2) + cbA) ^ rmA) << 4));\
        _Pragma("unroll") for (int p = 0; p < 4; p++) {                       \
            uint32_t t4[4];                                                   \
            ldsm4(t4,                                                         \
                  (Bs) + p * 2048 + bBase + ((((kc * 2) + cbB) ^ rmB) << 4)); \
            bfr[2*p][0]   = t4[0]; bfr[2*p][1]   = t4[1];                     \
            bfr[2*p+1][0] = t4[2]; bfr[2*p+1][1] = t4[3];                     \
        }                                                                     \
        _Pragma("unroll") for (int fm = 0; fm < 4; fm++)                      \
            _Pragma("unroll") for (int fn = 0; fn < 8; fn++)                  \
                mma_tf32(acc[fm][fn], afr[fm], bfr[fn]);                      \
    } }

// Fixed pipeline: LDG(c+1) in flight while COMPUTE(c) runs; STS after.
#define MAINLOOP(nch)                                                         \
    LOADG(0);                                                                 \
    STST(0);                                                                  \
    __syncthreads();                                                          \
    for (int c = 0; c < (nch); c++) {                                         \
        if (c + 1 < (nch)) LOADG((c + 1) * 32);                               \
        COMPUTE_CHUNK(sb + (c & 1) * 32768, sb + (c & 1) * 32768 + 16384);    \
        __syncthreads();                                                      \
        if (c + 1 < (nch)) {                                                  \
            STST(((c + 1) & 1) * 32768);                                      \
            __syncthreads();                                                  \
        }                                                                     \
    }

// ---------------------------------------------------------------------------
// Generic GEMM: D[M,Nn] = A @ Bt^T (+ bias). M%128==0, Nn%128==0, K%64==0.
// ---------------------------------------------------------------------------
__global__ __launch_bounds__(128, 2)
void mma_gemm(const float* __restrict__ A, const float* __restrict__ Bt,
              const float* __restrict__ bias, float* __restrict__ C,
              int M, int Nn, int K)
{
    const int bm = blockIdx.y * 128;
    const int bn = blockIdx.x * 128;
    GEMM_PROLOG();
    const float* pA0 = A  + (size_t)(bm + srow) * K + sc4 * 4;
    const float* pB0 = Bt + (size_t)(bn + srow) * K + sc4 * 4;
    const size_t strideJ = (size_t)16 * K;
    const int nch = K >> 5;
    MAINLOOP(nch);

    const int gid = lane >> 2, tig = lane & 3;
    #pragma unroll
    for (int fm = 0; fm < 4; fm++) {
        const int row = bm + wr * 64 + fm * 16 + gid;
        #pragma unroll
        for (int fn = 0; fn < 8; fn++) {
            const int col = bn + wc * 64 + fn * 8 + tig * 2;
            float b0 = 0.f, b1 = 0.f;
            if (bias != nullptr) { b0 = bias[col]; b1 = bias[col + 1]; }
            float2 v01, v23;
            v01.x = acc[fm][fn][0] + b0; v01.y = acc[fm][fn][1] + b1;
            v23.x = acc[fm][fn][2] + b0; v23.y = acc[fm][fn][3] + b1;
            *(float2*)(C + (size_t)row * Nn + col) = v01;
            *(float2*)(C + (size_t)(row + 8) * Nn + col) = v23;
        }
    }
}

// ---------------------------------------------------------------------------
// Split-K GEMM for skinny M=128 cases: C += A @ Bt^T over K slice (atomics).
// Grid: (Nn/128, M/128, nsplit). C must be zero-initialized.
// ---------------------------------------------------------------------------
__global__ __launch_bounds__(128, 2)
void mma_gemm_splitk(const float* __restrict__ A, const float* __restrict__ Bt,
                     float* __restrict__ C, int M, int Nn, int K, int klen)
{
    const int bm = blockIdx.y * 128;
    const int bn = blockIdx.x * 128;
    const int kbase = blockIdx.z * klen;
    GEMM_PROLOG();
    const float* pA0 = A  + (size_t)(bm + srow) * K + kbase + sc4 * 4;
    const float* pB0 = Bt + (size_t)(bn + srow) * K + kbase + sc4 * 4;
    const size_t strideJ = (size_t)16 * K;
    const int nch = klen >> 5;
    MAINLOOP(nch);

    const int gid = lane >> 2, tig = lane & 3;
    #pragma unroll
    for (int fm = 0; fm < 4; fm++) {
        const int row = bm + wr * 64 + fm * 16 + gid;
        #pragma unroll
        for (int fn = 0; fn < 8; fn++) {
            const int col = bn + wc * 64 + fn * 8 + tig * 2;
            atomicAdd(C + (size_t)row * Nn + col,       acc[fm][fn][0]);
            atomicAdd(C + (size_t)row * Nn + col + 1,   acc[fm][fn][1]);
            atomicAdd(C + (size_t)(row+8) * Nn + col,   acc[fm][fn][2]);
            atomicAdd(C + (size_t)(row+8) * Nn + col+1, acc[fm][fn][3]);
        }
    }
}

// ---------------------------------------------------------------------------
// Fused e_pre GEMM + scores epilogue. acc = gstar @ WhT^T (K=1024), then
// scores[row] += sum_col v[col]*tanh(acc + sproj[b,col] + cov[row]*Wc[col])
// ---------------------------------------------------------------------------
__global__ __launch_bounds__(128, 2)
void epre_scores_gemm(const float* __restrict__ A, const float* __restrict__ Bt,
                      const float* __restrict__ sproj,
                      const float* __restrict__ cov,
                      const float* __restrict__ Wc,
                      const float* __restrict__ v,
                      float* __restrict__ scores)
{
    const int bm = blockIdx.y * 128;
    const int bn = blockIdx.x * 128;
    GEMM_PROLOG();
    const float* pA0 = A  + (size_t)(bm + srow) * H_ + sc4 * 4;
    const float* pB0 = Bt + (size_t)(bn + srow) * H_ + sc4 * 4;
    const size_t strideJ = (size_t)16 * H_;
    MAINLOOP(H_ / 32);

    const int gid = lane >> 2, tig = lane & 3;
    float vv[16], wcv[16];
    #pragma unroll
    for (int fn = 0; fn < 8; fn++) {
        const int col = bn + wc * 64 + fn * 8 + tig * 2;
        vv[2*fn]   = v[col];      vv[2*fn+1]  = v[col + 1];
        wcv[2*fn]  = Wc[col];     wcv[2*fn+1] = Wc[col + 1];
    }
    #pragma unroll
    for (int fm = 0; fm < 4; fm++) {
        const int r0 = bm + wr * 64 + fm * 16 + gid;
        const int r1 = r0 + 8;
        const int b0i = r0 / N_, b1i = r1 / N_;
        const float c0 = cov[r0], c1 = cov[r1];
        const float* sp0 = sproj + (size_t)b0i * A_;
        const float* sp1 = sproj + (size_t)b1i * A_;
        float p0 = 0.f, p1 = 0.f;
        #pragma unroll
        for (int fn = 0; fn < 8; fn++) {
            const int col = bn + wc * 64 + fn * 8 + tig * 2;
            p0 += vv[2*fn]   * tanh_approx(acc[fm][fn][0] + sp0[col]     + c0 * wcv[2*fn]);
            p0 += vv[2*fn+1] * tanh_approx(acc[fm][fn][1] + sp0[col + 1] + c0 * wcv[2*fn+1]);
            p1 += vv[2*fn]   * tanh_approx(acc[fm][fn][2] + sp1[col]     + c1 * wcv[2*fn]);
            p1 += vv[2*fn+1] * tanh_approx(acc[fm][fn][3] + sp1[col + 1] + c1 * wcv[2*fn+1]);
        }
        p0 += __shfl_xor_sync(0xffffffffu, p0, 1);
        p0 += __shfl_xor_sync(0xffffffffu, p0, 2);
        p1 += __shfl_xor_sync(0xffffffffu, p1, 1);
        p1 += __shfl_xor_sync(0xffffffffu, p1, 2);
        if (tig == 0) {
            atomicAdd(scores + r0, p0);
            atomicAdd(scores + r1, p1);
        }
    }
}

// ---------------------------------------------------------------------------
__global__ __launch_bounds__(256) void transpose_kernel(
    const float* __restrict__ in, float* __restrict__ out, int R, int C)
{
    __shared__ float t[32][33];
    const int c0 = blockIdx.x * 32, r0 = blockIdx.y * 32;
    const int x = threadIdx.x, y = threadIdx.y;
    #pragma unroll
    for (int j = 0; j < 32; j += 8)
        t[y + j][x] = in[(size_t)(r0 + y + j) * C + c0 + x];
    __syncthreads();
    #pragma unroll
    for (int j = 0; j < 32; j += 8)
        out[(size_t)(c0 + y + j) * R + r0 + x] = t[x][y + j];
}

__global__ void bias_init_kernel(const float* __restrict__ b_gs,
                                 float* __restrict__ bias) {
    int h = blockIdx.x * blockDim.x + threadIdx.x;
    if (h < H_) bias[h] = b_gs[h];
}
__global__ void bias_acc_kernel(const float* __restrict__ b_g,
                                const float* __restrict__ W_gs,
                                float* __restrict__ bias) {
    int h = blockIdx.x * blockDim.x + threadIdx.x;
    int k0 = blockIdx.y * 256;
    float acc = 0.f;
    #pragma unroll 4
    for (int k = k0; k < k0 + 256; k++)
        acc += b_g[k] * W_gs[(size_t)k * H_ + h];
    atomicAdd(&bias[h], acc);
}

__global__ void zero_buf_kernel(float* __restrict__ p, int n) {
    int i = blockIdx.x * blockDim.x + threadIdx.x;
    if (i < n) p[i] = 0.f;
}

// softmax over N=49 + context c[b,h] = sum_n alpha[n] * gstar[b,n,h]
__global__ __launch_bounds__(256) void context_kernel(
    const float* __restrict__ scores, const float* __restrict__ gstar,
    float* __restrict__ out)
{
    const int b = blockIdx.x;
    __shared__ float alpha[N_];
    const int tid = threadIdx.x;

    if (tid == 0) {
        float m = -1e30f;
        #pragma unroll
        for (int n = 0; n < N_; n++) m = fmaxf(m, scores[b * N_ + n]);
        float s = 0.f;
        #pragma unroll
        for (int n = 0; n < N_; n++) {
            float e = expf(scores[b * N_ + n] - m);
            alpha[n] = e;
            s += e;
        }
        float inv = 1.f / s;
        #pragma unroll
        for (int n = 0; n < N_; n++) alpha[n] *= inv;
    }
    __syncthreads();

    const float* gb = gstar + (size_t)b * N_ * H_;
    for (int h = tid; h < H_; h += 256) {
        float acc = 0.f;
        #pragma unroll
        for (int n = 0; n < N_; n++)
            acc += alpha[n] * gb[(size_t)n * H_ + h];
        out[(size_t)b * H_ + h] = acc;
    }
}

// ---------------------------------------------------------------------------
extern "C" void kernel_launch(void* const* d_in, const int* in_sizes, int n_in,
                              void* d_out, int out_size) {
    const float* X    = (const float*)d_in[0];   // [6272,4096]
    const float* s_t  = (const float*)d_in[1];   // [128,1024]
    const float* cov  = (const float*)d_in[2];   // [6272]
    const float* W_g  = (const float*)d_in[3];   // [4096,4096]
    const float* b_g  = (const float*)d_in[4];   // [4096]
    const float* W_gs = (const float*)d_in[5];   // [4096,1024]
    const float* b_gs = (const float*)d_in[6];   // [1024]
    const float* W_h  = (const float*)d_in[7];   // [1024,1024]
    const float* W_s  = (const float*)d_in[8];   // [1024,1024]
    const float* W_c  = (const float*)d_in[9];   // [1024]
    const float* v    = (const float*)d_in[10];  // [1024]
    float* out = (float*)d_out;                  // [128,1024]

    float *WcombT, *biascomb, *gstar, *scratch, *WhT, *WsT, *sproj, *scores;
    cudaGetSymbolAddress((void**)&WcombT,   g_WcombT);
    cudaGetSymbolAddress((void**)&biascomb, g_biascomb);
    cudaGetSymbolAddress((void**)&gstar,    g_gstar);
    cudaGetSymbolAddress((void**)&scratch,  g_scratch);
    cudaGetSymbolAddress((void**)&WhT,      g_WhT);
    cudaGetSymbolAddress((void**)&WsT,      g_WsT);
    cudaGetSymbolAddress((void**)&sproj,    g_sproj);
    cudaGetSymbolAddress((void**)&scores,   g_scores);

    cudaFuncSetAttribute(mma_gemm,
                         cudaFuncAttributeMaxDynamicSharedMemorySize, TCSM);
    cudaFuncSetAttribute(mma_gemm_splitk,
                         cudaFuncAttributeMaxDynamicSharedMemorySize, TCSM);
    cudaFuncSetAttribute(epre_scores_gemm,
                         cudaFuncAttributeMaxDynamicSharedMemorySize, TCSM);

    float* WgsT = scratch;   // [1024,4096]

    dim3 tb(32, 8);
    transpose_kernel<<<dim3(H_ / 32, G_ / 32), tb>>>(W_gs, WgsT, G_, H_);
    transpose_kernel<<<dim3(A_ / 32, H_ / 32), tb>>>(W_h, WhT, H_, A_);
    transpose_kernel<<<dim3(A_ / 32, H_ / 32), tb>>>(W_s, WsT, H_, A_);

    bias_init_kernel<<<H_ / 256, 256>>>(b_gs, biascomb);
    bias_acc_kernel<<<dim3(H_ / 256, G_ / 256), 256>>>(b_g, W_gs, biascomb);
    zero_buf_kernel<<<(BN_ + 255) / 256, 256>>>(scores, BN_);
    zero_buf_kernel<<<(B_ * A_ + 255) / 256, 256>>>(sproj, B_ * A_);

    // WcombT[h,g] = sum_k WgsT[h,k] * W_g[g,k]   (M=1024, N=4096, K=4096)
    mma_gemm<<<dim3(G_ / 128, H_ / 128), 128, TCSM>>>(
        WgsT, W_g, nullptr, WcombT, H_, G_, G_);

    // g_star[m,h] = sum_k X[m,k] * WcombT[h,k] + bias[h]
    mma_gemm<<<dim3(H_ / 128, BN_ / 128), 128, TCSM>>>(
        X, WcombT, biascomb, gstar, BN_, H_, G_);

    // s_proj[b,a] = sum_h s_t[b,h] * WsT[a,h]   (split-K x8, atomic)
    mma_gemm_splitk<<<dim3(A_ / 128, 1, 8), 128, TCSM>>>(
        s_t, WsT, sproj, B_, A_, H_, H_ / 8);

    // fused: e_pre + tanh + v-dot -> scores (epre never materialized)
    epre_scores_gemm<<<dim3(A_ / 128, BN_ / 128), 128, TCSM>>>(
        gstar, WhT, sproj, cov, W_c, v, scores);

    context_kernel<<<B_, 256>>>(scores, gstar, out);
}

// round 6
// speedup vs baseline: 1.3138x; 1.0155x over previous
#include <cuda_runtime.h>
#include <math.h>
#include <stdint.h>

// ===========================================================================
// img_attention via warp-level TF32 mma.sync (compute_103-safe)
//   c_img = softmax(v . tanh(Wh g* + Ws s + Wc cov)) @ g*
//   g*    = X @ (W_g @ W_gs) + (b_g @ W_gs + b_gs)      [algebraic fold]
// GEMMs: D[m,n] = sum_k A[m,k] * Bt[n,k]  (both K-major)
// R6: single-sync pipelined mainloop (STS overlapped with MMA), batched
//     prologue kernel. Fused scores epilogue kept.
// ===========================================================================

#define B_   128
#define N_   49
#define G_   4096
#define H_   1024
#define A_   1024
#define BN_  (B_ * N_)   // 6272

__device__ float g_WcombT[H_ * G_];     // [1024,4096] = (W_g @ W_gs)^T
__device__ float g_biascomb[H_];
__device__ float g_gstar[BN_ * H_];     // [6272,1024]
__device__ float g_scratch[BN_ * A_];   // holds WgsT [1024,4096]
__device__ float g_WhT[A_ * H_];
__device__ float g_WsT[A_ * H_];
__device__ float g_sproj[B_ * A_];
__device__ float g_scores[BN_];

// ---------------------------------------------------------------------------
__device__ __forceinline__ uint32_t smem_u32(const void* p) {
    uint32_t a;
    asm("{ .reg .u64 t; cvta.to.shared.u64 t, %1; cvt.u32.u64 %0, t; }"
        : "=r"(a) : "l"(p));
    return a;
}
__device__ __forceinline__ float to_tf32(float x) {
    uint32_t u;
    asm("cvt.rna.tf32.f32 %0, %1;" : "=r"(u) : "f"(x));
    return __uint_as_float(u);
}
__device__ __forceinline__ float tanh_approx(float x) {
    float y;
    asm("tanh.approx.f32 %0, %1;" : "=f"(y) : "f"(x));
    return y;
}
__device__ __forceinline__ void ldsm4(uint32_t* r, uint32_t addr) {
    asm volatile("ldmatrix.sync.aligned.m8n8.x4.shared.b16 {%0,%1,%2,%3}, [%4];"
                 : "=r"(r[0]), "=r"(r[1]), "=r"(r[2]), "=r"(r[3]) : "r"(addr));
}
__device__ __forceinline__ void mma_tf32(float* d, const uint32_t* a,
                                         const uint32_t* b) {
    asm volatile(
        "mma.sync.aligned.m16n8k8.row.col.f32.tf32.tf32.f32 "
        "{%0,%1,%2,%3}, {%4,%5,%6,%7}, {%8,%9}, {%0,%1,%2,%3};"
        : "+f"(d[0]), "+f"(d[1]), "+f"(d[2]), "+f"(d[3])
        : "r"(a[0]), "r"(a[1]), "r"(a[2]), "r"(a[3]), "r"(b[0]), "r"(b[1]));
}

// ---------------------------------------------------------------------------
// GEMM machinery: 128x128 block, BK=32, 128 threads, 2x2 warps of 64x64.
// Double-buffered smem: 2 stages x (16KB A + 16KB B) = 64KB.
// ---------------------------------------------------------------------------
#define TCSM (2 * 32768)

#define GEMM_PROLOG()                                                         \
    extern __shared__ char smem[];                                            \
    const uint32_t sb = smem_u32(smem);                                       \
    const int tid = threadIdx.x;                                              \
    const int lane = tid & 31;                                                \
    const int wid = tid >> 5;                                                 \
    const int wr = wid >> 1;   /* 0..1 */                                     \
    const int wc = wid & 1;    /* 0..1 */                                     \
    const int srow = tid >> 3, sc4 = tid & 7;                                 \
    const uint32_t soff0 = (uint32_t)srow * 128 + ((sc4 ^ (srow & 7)) << 4);  \
    const int aRow = wr * 64 + ((lane >> 3) & 1) * 8 + (lane & 7);            \
    const int cbA = lane >> 4;                                                \
    const uint32_t aBase = (uint32_t)aRow * 128;                              \
    const int rmA = aRow & 7;                                                 \
    const int bRow = wc * 64 + (lane >> 4) * 8 + (lane & 7);                  \
    const int cbB = (lane >> 3) & 1;                                          \
    const uint32_t bBase = (uint32_t)bRow * 128;                              \
    const int rmB = bRow & 7;                                                 \
    float acc[4][8][4];                                                       \
    _Pragma("unroll") for (int i = 0; i < 4; i++)                             \
        _Pragma("unroll") for (int j = 0; j < 8; j++)                         \
            _Pragma("unroll") for (int q = 0; q < 4; q++) acc[i][j][q] = 0.f; \
    float4 sa[8], sbv[8];

#define LOADG(k0) {                                                           \
    _Pragma("unroll") for (int j = 0; j < 8; j++) {                           \
        sa[j]  = *(const float4*)(pA0 + j * strideJ + (k0));                  \
        sbv[j] = *(const float4*)(pB0 + j * strideJ + (k0));                  \
    } }

#define STST(stoff) {                                                         \
    _Pragma("unroll") for (int j = 0; j < 8; j++) {                           \
        float4 v4 = sa[j];                                                    \
        v4.x = to_tf32(v4.x); v4.y = to_tf32(v4.y);                           \
        v4.z = to_tf32(v4.z); v4.w = to_tf32(v4.w);                           \
        *(float4*)(smem + (stoff) + soff0 + j * 2048) = v4;                   \
        float4 w4 = sbv[j];                                                   \
        w4.x = to_tf32(w4.x); w4.y = to_tf32(w4.y);                           \
        w4.z = to_tf32(w4.z); w4.w = to_tf32(w4.w);                           \
        *(float4*)(smem + (stoff) + 16384 + soff0 + j * 2048) = w4;           \
    } }

#define COMPUTE_CHUNK(As, Bs) {                                               \
    _Pragma("unroll") for (int kc = 0; kc < 4; kc++) {                        \
        uint32_t afr[4][4], bfr[8][2];                                        \
        _Pragma("unroll") for (int fm = 0; fm < 4; fm++)                      \
            ldsm4(afr[fm],                                                    \
                  (As) + fm * 2048 + aBase + ((((kc * 2) + cbA) ^ rmA) << 4));\
        _Pragma("unroll") for (int p = 0; p < 4; p++) {                       \
            uint32_t t4[4];                                                   \
            ldsm4(t4,                                                         \
                  (Bs) + p * 2048 + bBase + ((((kc * 2) + cbB) ^ rmB) << 4)); \
            bfr[2*p][0]   = t4[0]; bfr[2*p][1]   = t4[1];                     \
            bfr[2*p+1][0] = t4[2]; bfr[2*p+1][1] = t4[3];                     \
        }                                                                     \
        _Pragma("unroll") for (int fm = 0; fm < 4; fm++)                      \
            _Pragma("unroll") for (int fn = 0; fn < 8; fn++)                  \
                mma_tf32(acc[fm][fn], afr[fm], bfr[fn]);                      \
    } }

// Single-sync pipeline: LDG(c+1) in flight during COMPUTE(c); STS(c+1)
// overlaps the compute tail; ONE barrier per chunk.
// Hazards: STST(c+1) writes buf[!(c&1)] whose readers (COMPUTE(c-1)) drained
// at the previous sync; COMPUTE(c) reads buf[c&1] written before that sync.
#define MAINLOOP(nch)                                                         \
    LOADG(0);                                                                 \
    STST(0);                                                                  \
    __syncthreads();                                                          \
    for (int c = 0; c < (nch); c++) {                                         \
        if (c + 1 < (nch)) LOADG((c + 1) * 32);                               \
        COMPUTE_CHUNK(sb + (c & 1) * 32768, sb + (c & 1) * 32768 + 16384);    \
        if (c + 1 < (nch)) {                                                  \
            STST(((c + 1) & 1) * 32768);                                      \
            __syncthreads();                                                  \
        }                                                                     \
    }

// ---------------------------------------------------------------------------
// Generic GEMM: D[M,Nn] = A @ Bt^T (+ bias). M%128==0, Nn%128==0, K%64==0.
// ---------------------------------------------------------------------------
__global__ __launch_bounds__(128, 2)
void mma_gemm(const float* __restrict__ A, const float* __restrict__ Bt,
              const float* __restrict__ bias, float* __restrict__ C,
              int M, int Nn, int K)
{
    const int bm = blockIdx.y * 128;
    const int bn = blockIdx.x * 128;
    GEMM_PROLOG();
    const float* pA0 = A  + (size_t)(bm + srow) * K + sc4 * 4;
    const float* pB0 = Bt + (size_t)(bn + srow) * K + sc4 * 4;
    const size_t strideJ = (size_t)16 * K;
    const int nch = K >> 5;
    MAINLOOP(nch);

    const int gid = lane >> 2, tig = lane & 3;
    #pragma unroll
    for (int fm = 0; fm < 4; fm++) {
        const int row = bm + wr * 64 + fm * 16 + gid;
        #pragma unroll
        for (int fn = 0; fn < 8; fn++) {
            const int col = bn + wc * 64 + fn * 8 + tig * 2;
            float b0 = 0.f, b1 = 0.f;
            if (bias != nullptr) { b0 = bias[col]; b1 = bias[col + 1]; }
            float2 v01, v23;
            v01.x = acc[fm][fn][0] + b0; v01.y = acc[fm][fn][1] + b1;
            v23.x = acc[fm][fn][2] + b0; v23.y = acc[fm][fn][3] + b1;
            *(float2*)(C + (size_t)row * Nn + col) = v01;
            *(float2*)(C + (size_t)(row + 8) * Nn + col) = v23;
        }
    }
}

// ---------------------------------------------------------------------------
// Split-K GEMM for skinny M=128: C += A @ Bt^T over K slice (atomics).
// ---------------------------------------------------------------------------
__global__ __launch_bounds__(128, 2)
void mma_gemm_splitk(const float* __restrict__ A, const float* __restrict__ Bt,
                     float* __restrict__ C, int M, int Nn, int K, int klen)
{
    const int bm = blockIdx.y * 128;
    const int bn = blockIdx.x * 128;
    const int kbase = blockIdx.z * klen;
    GEMM_PROLOG();
    const float* pA0 = A  + (size_t)(bm + srow) * K + kbase + sc4 * 4;
    const float* pB0 = Bt + (size_t)(bn + srow) * K + kbase + sc4 * 4;
    const size_t strideJ = (size_t)16 * K;
    const int nch = klen >> 5;
    MAINLOOP(nch);

    const int gid = lane >> 2, tig = lane & 3;
    #pragma unroll
    for (int fm = 0; fm < 4; fm++) {
        const int row = bm + wr * 64 + fm * 16 + gid;
        #pragma unroll
        for (int fn = 0; fn < 8; fn++) {
            const int col = bn + wc * 64 + fn * 8 + tig * 2;
            atomicAdd(C + (size_t)row * Nn + col,       acc[fm][fn][0]);
            atomicAdd(C + (size_t)row * Nn + col + 1,   acc[fm][fn][1]);
            atomicAdd(C + (size_t)(row+8) * Nn + col,   acc[fm][fn][2]);
            atomicAdd(C + (size_t)(row+8) * Nn + col+1, acc[fm][fn][3]);
        }
    }
}

// ---------------------------------------------------------------------------
// Fused e_pre GEMM + scores epilogue. acc = gstar @ WhT^T (K=1024), then
// scores[row] += sum_col v[col]*tanh(acc + sproj[b,col] + cov[row]*Wc[col])
// ---------------------------------------------------------------------------
__global__ __launch_bounds__(128, 2)
void epre_scores_gemm(const float* __restrict__ A, const float* __restrict__ Bt,
                      const float* __restrict__ sproj,
                      const float* __restrict__ cov,
                      const float* __restrict__ Wc,
                      const float* __restrict__ v,
                      float* __restrict__ scores)
{
    const int bm = blockIdx.y * 128;
    const int bn = blockIdx.x * 128;
    GEMM_PROLOG();
    const float* pA0 = A  + (size_t)(bm + srow) * H_ + sc4 * 4;
    const float* pB0 = Bt + (size_t)(bn + srow) * H_ + sc4 * 4;
    const size_t strideJ = (size_t)16 * H_;
    MAINLOOP(H_ / 32);

    const int gid = lane >> 2, tig = lane & 3;
    float vv[16], wcv[16];
    #pragma unroll
    for (int fn = 0; fn < 8; fn++) {
        const int col = bn + wc * 64 + fn * 8 + tig * 2;
        vv[2*fn]   = v[col];      vv[2*fn+1]  = v[col + 1];
        wcv[2*fn]  = Wc[col];     wcv[2*fn+1] = Wc[col + 1];
    }
    #pragma unroll
    for (int fm = 0; fm < 4; fm++) {
        const int r0 = bm + wr * 64 + fm * 16 + gid;
        const int r1 = r0 + 8;
        const int b0i = r0 / N_, b1i = r1 / N_;
        const float c0 = cov[r0], c1 = cov[r1];
        const float* sp0 = sproj + (size_t)b0i * A_;
        const float* sp1 = sproj + (size_t)b1i * A_;
        float p0 = 0.f, p1 = 0.f;
        #pragma unroll
        for (int fn = 0; fn < 8; fn++) {
            const int col = bn + wc * 64 + fn * 8 + tig * 2;
            p0 += vv[2*fn]   * tanh_approx(acc[fm][fn][0] + sp0[col]     + c0 * wcv[2*fn]);
            p0 += vv[2*fn+1] * tanh_approx(acc[fm][fn][1] + sp0[col + 1] + c0 * wcv[2*fn+1]);
            p1 += vv[2*fn]   * tanh_approx(acc[fm][fn][2] + sp1[col]     + c1 * wcv[2*fn]);
            p1 += vv[2*fn+1] * tanh_approx(acc[fm][fn][3] + sp1[col + 1] + c1 * wcv[2*fn+1]);
        }
        p0 += __shfl_xor_sync(0xffffffffu, p0, 1);
        p0 += __shfl_xor_sync(0xffffffffu, p0, 2);
        p1 += __shfl_xor_sync(0xffffffffu, p1, 1);
        p1 += __shfl_xor_sync(0xffffffffu, p1, 2);
        if (tig == 0) {
            atomicAdd(scores + r0, p0);
            atomicAdd(scores + r1, p1);
        }
    }
}

// ---------------------------------------------------------------------------
// Batched prologue: 3 transposes + zero scores + zero sproj in ONE launch.
// Block layout (256 thr, 32x8):
//   [0, 4096)        : W_gs [4096,1024] -> WgsT tiles (32 x-tiles, 128 y)
//   [4096, 5120)     : W_h  [1024,1024] -> WhT
//   [5120, 6144)     : W_s  [1024,1024] -> WsT
//   [6144, 6144+25)  : zero scores (6272)
//   [6169, 6169+512) : zero sproj (131072)
// ---------------------------------------------------------------------------
#define PREP_T1 4096
#define PREP_T2 5120
#define PREP_T3 6144
#define PREP_ZS (PREP_T3 + 25)
#define PREP_END (PREP_ZS + 512)

__device__ __forceinline__ void do_transpose32(
    const float* __restrict__ in, float* __restrict__ out,
    int R, int C, int tx, int ty)
{
    __shared__ float t[32][33];
    const int c0 = tx * 32, r0 = ty * 32;
    const int x = threadIdx.x & 31, y = (threadIdx.x >> 5) ;
    #pragma unroll
    for (int j = 0; j < 32; j += 8)
        t[y + j][x] = in[(size_t)(r0 + y + j) * C + c0 + x];
    __syncthreads();
    #pragma unroll
    for (int j = 0; j < 32; j += 8)
        out[(size_t)(c0 + y + j) * R + r0 + x] = t[x][y + j];
}

__global__ __launch_bounds__(256) void prep_kernel(
    const float* __restrict__ W_gs, float* __restrict__ WgsT,
    const float* __restrict__ W_h,  float* __restrict__ WhT,
    const float* __restrict__ W_s,  float* __restrict__ WsT,
    float* __restrict__ scores, float* __restrict__ sproj)
{
    const int bid = blockIdx.x;
    if (bid < PREP_T1) {
        do_transpose32(W_gs, WgsT, G_, H_, bid & 31, bid >> 5);
    } else if (bid < PREP_T2) {
        const int b = bid - PREP_T1;
        do_transpose32(W_h, WhT, H_, A_, b & 31, b >> 5);
    } else if (bid < PREP_T3) {
        const int b = bid - PREP_T2;
        do_transpose32(W_s, WsT, H_, A_, b & 31, b >> 5);
    } else if (bid < PREP_ZS) {
        const int i = (bid - PREP_T3) * 256 + threadIdx.x;
        if (i < BN_) scores[i] = 0.f;
    } else {
        const int i = (bid - PREP_ZS) * 256 + threadIdx.x;
        sproj[i] = 0.f;
    }
}

__global__ void bias_init_kernel(const float* __restrict__ b_gs,
                                 float* __restrict__ bias) {
    int h = blockIdx.x * blockDim.x + threadIdx.x;
    if (h < H_) bias[h] = b_gs[h];
}
__global__ void bias_acc_kernel(const float* __restrict__ b_g,
                                const float* __restrict__ W_gs,
                                float* __restrict__ bias) {
    int h = blockIdx.x * blockDim.x + threadIdx.x;
    int k0 = blockIdx.y * 256;
    float acc = 0.f;
    #pragma unroll 4
    for (int k = k0; k < k0 + 256; k++)
        acc += b_g[k] * W_gs[(size_t)k * H_ + h];
    atomicAdd(&bias[h], acc);
}

// softmax over N=49 + context c[b,h] = sum_n alpha[n] * gstar[b,n,h]
__global__ __launch_bounds__(256) void context_kernel(
    const float* __restrict__ scores, const float* __restrict__ gstar,
    float* __restrict__ out)
{
    const int b = blockIdx.x;
    __shared__ float alpha[N_];
    const int tid = threadIdx.x;

    if (tid == 0) {
        float m = -1e30f;
        #pragma unroll
        for (int n = 0; n < N_; n++) m = fmaxf(m, scores[b * N_ + n]);
        float s = 0.f;
        #pragma unroll
        for (int n = 0; n < N_; n++) {
            float e = expf(scores[b * N_ + n] - m);
            alpha[n] = e;
            s += e;
        }
        float inv = 1.f / s;
        #pragma unroll
        for (int n = 0; n < N_; n++) alpha[n] *= inv;
    }
    __syncthreads();

    const float* gb = gstar + (size_t)b * N_ * H_;
    for (int h = tid; h < H_; h += 256) {
        float acc = 0.f;
        #pragma unroll
        for (int n = 0; n < N_; n++)
            acc += alpha[n] * gb[(size_t)n * H_ + h];
        out[(size_t)b * H_ + h] = acc;
    }
}

// ---------------------------------------------------------------------------
extern "C" void kernel_launch(void* const* d_in, const int* in_sizes, int n_in,
                              void* d_out, int out_size) {
    const float* X    = (const float*)d_in[0];   // [6272,4096]
    const float* s_t  = (const float*)d_in[1];   // [128,1024]
    const float* cov  = (const float*)d_in[2];   // [6272]
    const float* W_g  = (const float*)d_in[3];   // [4096,4096]
    const float* b_g  = (const float*)d_in[4];   // [4096]
    const float* W_gs = (const float*)d_in[5];   // [4096,1024]
    const float* b_gs = (const float*)d_in[6];   // [1024]
    const float* W_h  = (const float*)d_in[7];   // [1024,1024]
    const float* W_s  = (const float*)d_in[8];   // [1024,1024]
    const float* W_c  = (const float*)d_in[9];   // [1024]
    const float* v    = (const float*)d_in[10];  // [1024]
    float* out = (float*)d_out;                  // [128,1024]

    float *WcombT, *biascomb, *gstar, *scratch, *WhT, *WsT, *sproj, *scores;
    cudaGetSymbolAddress((void**)&WcombT,   g_WcombT);
    cudaGetSymbolAddress((void**)&biascomb, g_biascomb);
    cudaGetSymbolAddress((void**)&gstar,    g_gstar);
    cudaGetSymbolAddress((void**)&scratch,  g_scratch);
    cudaGetSymbolAddress((void**)&WhT,      g_WhT);
    cudaGetSymbolAddress((void**)&WsT,      g_WsT);
    cudaGetSymbolAddress((void**)&sproj,    g_sproj);
    cudaGetSymbolAddress((void**)&scores,   g_scores);

    cudaFuncSetAttribute(mma_gemm,
                         cudaFuncAttributeMaxDynamicSharedMemorySize, TCSM);
    cudaFuncSetAttribute(mma_gemm_splitk,
                         cudaFuncAttributeMaxDynamicSharedMemorySize, TCSM);
    cudaFuncSetAttribute(epre_scores_gemm,
                         cudaFuncAttributeMaxDynamicSharedMemorySize, TCSM);

    float* WgsT = scratch;   // [1024,4096]

    // batched prologue: 3 transposes + zero scores/sproj
    prep_kernel<<<PREP_END, 256>>>(W_gs, WgsT, W_h, WhT, W_s, WsT,
                                   scores, sproj);
    bias_init_kernel<<<H_ / 256, 256>>>(b_gs, biascomb);
    bias_acc_kernel<<<dim3(H_ / 256, G_ / 256), 256>>>(b_g, W_gs, biascomb);

    // WcombT[h,g] = sum_k WgsT[h,k] * W_g[g,k]   (M=1024, N=4096, K=4096)
    mma_gemm<<<dim3(G_ / 128, H_ / 128), 128, TCSM>>>(
        WgsT, W_g, nullptr, WcombT, H_, G_, G_);

    // g_star[m,h] = sum_k X[m,k] * WcombT[h,k] + bias[h]
    mma_gemm<<<dim3(H_ / 128, BN_ / 128), 128, TCSM>>>(
        X, WcombT, biascomb, gstar, BN_, H_, G_);

    // s_proj[b,a] = sum_h s_t[b,h] * WsT[a,h]   (split-K x8, atomic)
    mma_gemm_splitk<<<dim3(A_ / 128, 1, 8), 128, TCSM>>>(
        s_t, WsT, sproj, B_, A_, H_, H_ / 8);

    // fused: e_pre + tanh + v-dot -> scores (epre never materialized)
    epre_scores_gemm<<<dim3(A_ / 128, BN_ / 128), 128, TCSM>>>(
        gstar, WhT, sproj, cov, W_c, v, scores);

    context_kernel<<<B_, 256>>>(scores, gstar, out);
}

// round 7
// speedup vs baseline: 1.5181x; 1.1555x over previous
#include <cuda_runtime.h>
#include <math.h>
#include <stdint.h>

// ===========================================================================
// img_attention via warp-level TF32 mma.sync (compute_103-safe)
//   c_img = softmax(v . tanh(Wh g* + Ws s + Wc cov)) @ g*
//   g*    = X @ (W_g @ W_gs) + (b_g @ W_gs + b_gs)      [algebraic fold]
// GEMMs: D[m,n] = sum_k A[m,k] * Bt[n,k]  (both K-major)
// R7: cp.async 3-stage mainloop, operands pre-rounded to TF32 (RNA) in gmem,
//     no in-loop staging/cvt/STS. Fused scores epilogue kept.
// ===========================================================================

#define B_   128
#define N_   49
#define G_   4096
#define H_   1024
#define A_   1024
#define BN_  (B_ * N_)   // 6272

__device__ float g_WcombT[H_ * G_];     // [1024,4096] (rounded)
__device__ float g_biascomb[H_];
__device__ float g_gstar[BN_ * H_];     // [6272,1024] (rounded)
__device__ float g_WgsT[H_ * G_];       // W_gs^T rounded [1024,4096]
__device__ float g_WhT[A_ * H_];        // rounded
__device__ float g_WsT[A_ * H_];        // rounded
__device__ float g_Xr[BN_ * G_];        // X rounded [6272,4096]
__device__ float g_Wgr[G_ * G_];        // W_g rounded [4096,4096]
__device__ float g_str[B_ * H_];        // s_t rounded
__device__ float g_sproj[B_ * A_];
__device__ float g_scores[BN_];

// ---------------------------------------------------------------------------
__device__ __forceinline__ uint32_t smem_u32(const void* p) {
    uint32_t a;
    asm("{ .reg .u64 t; cvta.to.shared.u64 t, %1; cvt.u32.u64 %0, t; }"
        : "=r"(a) : "l"(p));
    return a;
}
__device__ __forceinline__ float to_tf32(float x) {
    uint32_t u;
    asm("cvt.rna.tf32.f32 %0, %1;" : "=r"(u) : "f"(x));
    return __uint_as_float(u);
}
__device__ __forceinline__ float tanh_approx(float x) {
    float y;
    asm("tanh.approx.f32 %0, %1;" : "=f"(y) : "f"(x));
    return y;
}
__device__ __forceinline__ void ldsm4(uint32_t* r, uint32_t addr) {
    asm volatile("ldmatrix.sync.aligned.m8n8.x4.shared.b16 {%0,%1,%2,%3}, [%4];"
                 : "=r"(r[0]), "=r"(r[1]), "=r"(r[2]), "=r"(r[3]) : "r"(addr));
}
__device__ __forceinline__ void mma_tf32(float* d, const uint32_t* a,
                                         const uint32_t* b) {
    asm volatile(
        "mma.sync.aligned.m16n8k8.row.col.f32.tf32.tf32.f32 "
        "{%0,%1,%2,%3}, {%4,%5,%6,%7}, {%8,%9}, {%0,%1,%2,%3};"
        : "+f"(d[0]), "+f"(d[1]), "+f"(d[2]), "+f"(d[3])
        : "r"(a[0]), "r"(a[1]), "r"(a[2]), "r"(a[3]), "r"(b[0]), "r"(b[1]));
}
#define CPA(dst, src) \
    asm volatile("cp.async.cg.shared.global [%0], [%1], 16;" \
                 :: "r"(dst), "l"(src) : "memory")
#define CPCOMMIT() asm volatile("cp.async.commit_group;" ::: "memory")
#define CPWAIT1()  asm volatile("cp.async.wait_group 1;" ::: "memory")
#define CPWAIT0()  asm volatile("cp.async.wait_group 0;" ::: "memory")

// ---------------------------------------------------------------------------
// GEMM machinery: 128x128 block, BK=32, 128 threads, 2x2 warps of 64x64.
// 3-stage cp.async ring: 3 x (16KB A + 16KB B) = 96KB.
// ---------------------------------------------------------------------------
#define STAGE_B 32768
#define TCSM (3 * STAGE_B)

#define GEMM_PROLOG()                                                         \
    extern __shared__ char smem[];                                            \
    const uint32_t sb = smem_u32(smem);                                       \
    const int tid = threadIdx.x;                                              \
    const int lane = tid & 31;                                                \
    const int wid = tid >> 5;                                                 \
    const int wr = wid >> 1;   /* 0..1 */                                     \
    const int wc = wid & 1;    /* 0..1 */                                     \
    const int srow = tid >> 3, sc4 = tid & 7;                                 \
    const uint32_t soff0 = (uint32_t)srow * 128 + ((sc4 ^ (srow & 7)) << 4);  \
    const int aRow = wr * 64 + ((lane >> 3) & 1) * 8 + (lane & 7);            \
    const int cbA = lane >> 4;                                                \
    const uint32_t aBase = (uint32_t)aRow * 128;                              \
    const int rmA = aRow & 7;                                                 \
    const int bRow = wc * 64 + (lane >> 4) * 8 + (lane & 7);                  \
    const int cbB = (lane >> 3) & 1;                                          \
    const uint32_t bBase = (uint32_t)bRow * 128;                              \
    const int rmB = bRow & 7;                                                 \
    float acc[4][8][4];                                                       \
    _Pragma("unroll") for (int i = 0; i < 4; i++)                             \
        _Pragma("unroll") for (int j = 0; j < 8; j++)                         \
            _Pragma("unroll") for (int q = 0; q < 4; q++) acc[i][j][q] = 0.f;

// issue one 128x32 A tile + 128x32 B tile into stage at smem addr `sbase`
#define ISSUE_STAGE(sbase, k0) {                                              \
    _Pragma("unroll") for (int j = 0; j < 8; j++) {                           \
        CPA((sbase) + soff0 + j * 2048,         pA0 + (k0) + j * strideJ);    \
        CPA((sbase) + 16384 + soff0 + j * 2048, pB0 + (k0) + j * strideJ);    \
    }                                                                         \
    CPCOMMIT(); }

#define COMPUTE_CHUNK(As, Bs) {                                               \
    _Pragma("unroll") for (int kc = 0; kc < 4; kc++) {                        \
        uint32_t afr[4][4], bfr[8][2];                                        \
        _Pragma("unroll") for (int fm = 0; fm < 4; fm++)                      \
            ldsm4(afr[fm],                                                    \
                  (As) + fm * 2048 + aBase + ((((kc * 2) + cbA) ^ rmA) << 4));\
        _Pragma("unroll") for (int p = 0; p < 4; p++) {                       \
            uint32_t t4[4];                                                   \
            ldsm4(t4,                                                         \
                  (Bs) + p * 2048 + bBase + ((((kc * 2) + cbB) ^ rmB) << 4)); \
            bfr[2*p][0]   = t4[0]; bfr[2*p][1]   = t4[1];                     \
            bfr[2*p+1][0] = t4[2]; bfr[2*p+1][1] = t4[3];                     \
        }                                                                     \
        _Pragma("unroll") for (int fm = 0; fm < 4; fm++)                      \
            _Pragma("unroll") for (int fn = 0; fn < 8; fn++)                  \
                mma_tf32(acc[fm][fn], afr[fm], bfr[fn]);                      \
    } }

// 3-stage pipeline; requires nch >= 2 (min here is 4).
// wait_group(1) at iter c completes group c (pending {c, c+1}); last iter
// uses wait_group(0). Buffer (c+2)%3 overwrite is fenced by the barrier:
// its readers (COMPUTE(c-1)) finished before this iteration's sync.
#define MAINLOOP(nch)                                                         \
    ISSUE_STAGE(sb, 0);                                                       \
    ISSUE_STAGE(sb + STAGE_B, 32);                                            \
    { int cs = 0, is = 2;                                                     \
    for (int c = 0; c < (nch); c++) {                                         \
        if (c == (nch) - 1) { CPWAIT0(); } else { CPWAIT1(); }                \
        __syncthreads();                                                      \
        if (c + 2 < (nch)) {                                                  \
            ISSUE_STAGE(sb + is * STAGE_B, (c + 2) * 32);                     \
            is = (is == 2) ? 0 : is + 1;                                      \
        }                                                                     \
        COMPUTE_CHUNK(sb + cs * STAGE_B, sb + cs * STAGE_B + 16384);          \
        cs = (cs == 2) ? 0 : cs + 1;                                          \
    } }

// ---------------------------------------------------------------------------
// Generic GEMM: D = A @ Bt^T (+ bias), optional TF32-rounded store.
// ---------------------------------------------------------------------------
__global__ __launch_bounds__(128, 2)
void mma_gemm(const float* __restrict__ A, const float* __restrict__ Bt,
              const float* __restrict__ bias, float* __restrict__ C,
              int M, int Nn, int K, int roundC)
{
    const int bm = blockIdx.y * 128;
    const int bn = blockIdx.x * 128;
    GEMM_PROLOG();
    const float* pA0 = A  + (size_t)(bm + srow) * K + sc4 * 4;
    const float* pB0 = Bt + (size_t)(bn + srow) * K + sc4 * 4;
    const size_t strideJ = (size_t)16 * K;
    const int nch = K >> 5;
    MAINLOOP(nch);

    const int gid = lane >> 2, tig = lane & 3;
    #pragma unroll
    for (int fm = 0; fm < 4; fm++) {
        const int row = bm + wr * 64 + fm * 16 + gid;
        #pragma unroll
        for (int fn = 0; fn < 8; fn++) {
            const int col = bn + wc * 64 + fn * 8 + tig * 2;
            float b0 = 0.f, b1 = 0.f;
            if (bias != nullptr) { b0 = bias[col]; b1 = bias[col + 1]; }
            float2 v01, v23;
            v01.x = acc[fm][fn][0] + b0; v01.y = acc[fm][fn][1] + b1;
            v23.x = acc[fm][fn][2] + b0; v23.y = acc[fm][fn][3] + b1;
            if (roundC) {
                v01.x = to_tf32(v01.x); v01.y = to_tf32(v01.y);
                v23.x = to_tf32(v23.x); v23.y = to_tf32(v23.y);
            }
            *(float2*)(C + (size_t)row * Nn + col) = v01;
            *(float2*)(C + (size_t)(row + 8) * Nn + col) = v23;
        }
    }
}

// ---------------------------------------------------------------------------
// Split-K GEMM for skinny M=128: C += A @ Bt^T over K slice (atomics).
// ---------------------------------------------------------------------------
__global__ __launch_bounds__(128, 2)
void mma_gemm_splitk(const float* __restrict__ A, const float* __restrict__ Bt,
                     float* __restrict__ C, int M, int Nn, int K, int klen)
{
    const int bm = blockIdx.y * 128;
    const int bn = blockIdx.x * 128;
    const int kbase = blockIdx.z * klen;
    GEMM_PROLOG();
    const float* pA0 = A  + (size_t)(bm + srow) * K + kbase + sc4 * 4;
    const float* pB0 = Bt + (size_t)(bn + srow) * K + kbase + sc4 * 4;
    const size_t strideJ = (size_t)16 * K;
    const int nch = klen >> 5;
    MAINLOOP(nch);

    const int gid = lane >> 2, tig = lane & 3;
    #pragma unroll
    for (int fm = 0; fm < 4; fm++) {
        const int row = bm + wr * 64 + fm * 16 + gid;
        #pragma unroll
        for (int fn = 0; fn < 8; fn++) {
            const int col = bn + wc * 64 + fn * 8 + tig * 2;
            atomicAdd(C + (size_t)row * Nn + col,       acc[fm][fn][0]);
            atomicAdd(C + (size_t)row * Nn + col + 1,   acc[fm][fn][1]);
            atomicAdd(C + (size_t)(row+8) * Nn + col,   acc[fm][fn][2]);
            atomicAdd(C + (size_t)(row+8) * Nn + col+1, acc[fm][fn][3]);
        }
    }
}

// ---------------------------------------------------------------------------
// Fused e_pre GEMM + scores epilogue. acc = gstar @ WhT^T (K=1024), then
// scores[row] += sum_col v[col]*tanh(acc + sproj[b,col] + cov[row]*Wc[col])
// ---------------------------------------------------------------------------
__global__ __launch_bounds__(128, 2)
void epre_scores_gemm(const float* __restrict__ A, const float* __restrict__ Bt,
                      const float* __restrict__ sproj,
                      const float* __restrict__ cov,
                      const float* __restrict__ Wc,
                      const float* __restrict__ v,
                      float* __restrict__ scores)
{
    const int bm = blockIdx.y * 128;
    const int bn = blockIdx.x * 128;
    GEMM_PROLOG();
    const float* pA0 = A  + (size_t)(bm + srow) * H_ + sc4 * 4;
    const float* pB0 = Bt + (size_t)(bn + srow) * H_ + sc4 * 4;
    const size_t strideJ = (size_t)16 * H_;
    MAINLOOP(H_ / 32);

    const int gid = lane >> 2, tig = lane & 3;
    float vv[16], wcv[16];
    #pragma unroll
    for (int fn = 0; fn < 8; fn++) {
        const int col = bn + wc * 64 + fn * 8 + tig * 2;
        vv[2*fn]   = v[col];      vv[2*fn+1]  = v[col + 1];
        wcv[2*fn]  = Wc[col];     wcv[2*fn+1] = Wc[col + 1];
    }
    #pragma unroll
    for (int fm = 0; fm < 4; fm++) {
        const int r0 = bm + wr * 64 + fm * 16 + gid;
        const int r1 = r0 + 8;
        const int b0i = r0 / N_, b1i = r1 / N_;
        const float c0 = cov[r0], c1 = cov[r1];
        const float* sp0 = sproj + (size_t)b0i * A_;
        const float* sp1 = sproj + (size_t)b1i * A_;
        float p0 = 0.f, p1 = 0.f;
        #pragma unroll
        for (int fn = 0; fn < 8; fn++) {
            const int col = bn + wc * 64 + fn * 8 + tig * 2;
            p0 += vv[2*fn]   * tanh_approx(acc[fm][fn][0] + sp0[col]     + c0 * wcv[2*fn]);
            p0 += vv[2*fn+1] * tanh_approx(acc[fm][fn][1] + sp0[col + 1] + c0 * wcv[2*fn+1]);
            p1 += vv[2*fn]   * tanh_approx(acc[fm][fn][2] + sp1[col]     + c1 * wcv[2*fn]);
            p1 += vv[2*fn+1] * tanh_approx(acc[fm][fn][3] + sp1[col + 1] + c1 * wcv[2*fn+1]);
        }
        p0 += __shfl_xor_sync(0xffffffffu, p0, 1);
        p0 += __shfl_xor_sync(0xffffffffu, p0, 2);
        p1 += __shfl_xor_sync(0xffffffffu, p1, 1);
        p1 += __shfl_xor_sync(0xffffffffu, p1, 2);
        if (tig == 0) {
            atomicAdd(scores + r0, p0);
            atomicAdd(scores + r1, p1);
        }
    }
}

// ---------------------------------------------------------------------------
// Batched prologue: transposes (rounded), zero-fills, and TF32 rounding
// passes over X, W_g, s_t — all in ONE launch.
// ---------------------------------------------------------------------------
#define PREP_T1 4096
#define PREP_T2 (PREP_T1 + 1024)
#define PREP_T3 (PREP_T2 + 1024)
#define PREP_ZS (PREP_T3 + 25)
#define PREP_ZP (PREP_ZS + 512)
#define PREP_RX (PREP_ZP + 25088)      // X: 6272*4096/4/256
#define PREP_RW (PREP_RX + 16384)      // W_g: 4096*4096/4/256
#define PREP_RS (PREP_RW + 128)        // s_t: 128*1024/4/256
#define PREP_END PREP_RS

__device__ __forceinline__ void do_transpose32r(
    const float* __restrict__ in, float* __restrict__ out,
    int R, int C, int tx, int ty)
{
    __shared__ float t[32][33];
    const int c0 = tx * 32, r0 = ty * 32;
    const int x = threadIdx.x & 31, y = (threadIdx.x >> 5);
    #pragma unroll
    for (int j = 0; j < 32; j += 8)
        t[y + j][x] = in[(size_t)(r0 + y + j) * C + c0 + x];
    __syncthreads();
    #pragma unroll
    for (int j = 0; j < 32; j += 8)
        out[(size_t)(c0 + y + j) * R + r0 + x] = to_tf32(t[x][y + j]);
}

__device__ __forceinline__ void round4(const float* __restrict__ in,
                                       float* __restrict__ out, int i) {
    float4 x = *(const float4*)(in + (size_t)i * 4);
    x.x = to_tf32(x.x); x.y = to_tf32(x.y);
    x.z = to_tf32(x.z); x.w = to_tf32(x.w);
    *(float4*)(out + (size_t)i * 4) = x;
}

__global__ __launch_bounds__(256) void prep_kernel(
    const float* __restrict__ W_gs, float* __restrict__ WgsT,
    const float* __restrict__ W_h,  float* __restrict__ WhT,
    const float* __restrict__ W_s,  float* __restrict__ WsT,
    const float* __restrict__ X,    float* __restrict__ Xr,
    const float* __restrict__ W_g,  float* __restrict__ Wgr,
    const float* __restrict__ s_t,  float* __restrict__ str,
    float* __restrict__ scores, float* __restrict__ sproj)
{
    const int bid = blockIdx.x;
    if (bid < PREP_T1) {
        do_transpose32r(W_gs, WgsT, G_, H_, bid & 31, bid >> 5);
    } else if (bid < PREP_T2) {
        const int b = bid - PREP_T1;
        do_transpose32r(W_h, WhT, H_, A_, b & 31, b >> 5);
    } else if (bid < PREP_T3) {
        const int b = bid - PREP_T2;
        do_transpose32r(W_s, WsT, H_, A_, b & 31, b >> 5);
    } else if (bid < PREP_ZS) {
        const int i = (bid - PREP_T3) * 256 + threadIdx.x;
        if (i < BN_) scores[i] = 0.f;
    } else if (bid < PREP_ZP) {
        const int i = (bid - PREP_ZS) * 256 + threadIdx.x;
        sproj[i] = 0.f;
    } else if (bid < PREP_RX) {
        round4(X, Xr, (bid - PREP_ZP) * 256 + threadIdx.x);
    } else if (bid < PREP_RW) {
        round4(W_g, Wgr, (bid - PREP_RX) * 256 + threadIdx.x);
    } else {
        round4(s_t, str, (bid - PREP_RW) * 256 + threadIdx.x);
    }
}

__global__ void bias_init_kernel(const float* __restrict__ b_gs,
                                 float* __restrict__ bias) {
    int h = blockIdx.x * blockDim.x + threadIdx.x;
    if (h < H_) bias[h] = b_gs[h];
}
__global__ void bias_acc_kernel(const float* __restrict__ b_g,
                                const float* __restrict__ W_gs,
                                float* __restrict__ bias) {
    int h = blockIdx.x * blockDim.x + threadIdx.x;
    int k0 = blockIdx.y * 256;
    float acc = 0.f;
    #pragma unroll 4
    for (int k = k0; k < k0 + 256; k++)
        acc += b_g[k] * W_gs[(size_t)k * H_ + h];
    atomicAdd(&bias[h], acc);
}

// softmax over N=49 + context c[b,h] = sum_n alpha[n] * gstar[b,n,h]
__global__ __launch_bounds__(256) void context_kernel(
    const float* __restrict__ scores, const float* __restrict__ gstar,
    float* __restrict__ out)
{
    const int b = blockIdx.x;
    __shared__ float alpha[N_];
    const int tid = threadIdx.x;

    if (tid == 0) {
        float m = -1e30f;
        #pragma unroll
        for (int n = 0; n < N_; n++) m = fmaxf(m, scores[b * N_ + n]);
        float s = 0.f;
        #pragma unroll
        for (int n = 0; n < N_; n++) {
            float e = expf(scores[b * N_ + n] - m);
            alpha[n] = e;
            s += e;
        }
        float inv = 1.f / s;
        #pragma unroll
        for (int n = 0; n < N_; n++) alpha[n] *= inv;
    }
    __syncthreads();

    const float* gb = gstar + (size_t)b * N_ * H_;
    for (int h = tid; h < H_; h += 256) {
        float acc = 0.f;
        #pragma unroll
        for (int n = 0; n < N_; n++)
            acc += alpha[n] * gb[(size_t)n * H_ + h];
        out[(size_t)b * H_ + h] = acc;
    }
}

// ---------------------------------------------------------------------------
extern "C" void kernel_launch(void* const* d_in, const int* in_sizes, int n_in,
                              void* d_out, int out_size) {
    const float* X    = (const float*)d_in[0];   // [6272,4096]
    const float* s_t  = (const float*)d_in[1];   // [128,1024]
    const float* cov  = (const float*)d_in[2];   // [6272]
    const float* W_g  = (const float*)d_in[3];   // [4096,4096]
    const float* b_g  = (const float*)d_in[4];   // [4096]
    const float* W_gs = (const float*)d_in[5];   // [4096,1024]
    const float* b_gs = (const float*)d_in[6];   // [1024]
    const float* W_h  = (const float*)d_in[7];   // [1024,1024]
    const float* W_s  = (const float*)d_in[8];   // [1024,1024]
    const float* W_c  = (const float*)d_in[9];   // [1024]
    const float* v    = (const float*)d_in[10];  // [1024]
    float* out = (float*)d_out;                  // [128,1024]

    float *WcombT, *biascomb, *gstar, *WgsT, *WhT, *WsT;
    float *Xr, *Wgr, *str, *sproj, *scores;
    cudaGetSymbolAddress((void**)&WcombT,   g_WcombT);
    cudaGetSymbolAddress((void**)&biascomb, g_biascomb);
    cudaGetSymbolAddress((void**)&gstar,    g_gstar);
    cudaGetSymbolAddress((void**)&WgsT,     g_WgsT);
    cudaGetSymbolAddress((void**)&WhT,      g_WhT);
    cudaGetSymbolAddress((void**)&WsT,      g_WsT);
    cudaGetSymbolAddress((void**)&Xr,       g_Xr);
    cudaGetSymbolAddress((void**)&Wgr,      g_Wgr);
    cudaGetSymbolAddress((void**)&str,      g_str);
    cudaGetSymbolAddress((void**)&sproj,    g_sproj);
    cudaGetSymbolAddress((void**)&scores,   g_scores);

    cudaFuncSetAttribute(mma_gemm,
                         cudaFuncAttributeMaxDynamicSharedMemorySize, TCSM);
    cudaFuncSetAttribute(mma_gemm_splitk,
                         cudaFuncAttributeMaxDynamicSharedMemorySize, TCSM);
    cudaFuncSetAttribute(epre_scores_gemm,
                         cudaFuncAttributeMaxDynamicSharedMemorySize, TCSM);

    // prologue: transposes (rounded), zero-fills, rounding of X/W_g/s_t
    prep_kernel<<<PREP_END, 256>>>(W_gs, WgsT, W_h, WhT, W_s, WsT,
                                   X, Xr, W_g, Wgr, s_t, str, scores, sproj);
    bias_init_kernel<<<H_ / 256, 256>>>(b_gs, biascomb);
    bias_acc_kernel<<<dim3(H_ / 256, G_ / 256), 256>>>(b_g, W_gs, biascomb);

    // WcombT[h,g] = sum_k WgsT[h,k] * Wgr[g,k]  (rounded store)
    mma_gemm<<<dim3(G_ / 128, H_ / 128), 128, TCSM>>>(
        WgsT, Wgr, nullptr, WcombT, H_, G_, G_, 1);

    // g_star[m,h] = sum_k Xr[m,k] * WcombT[h,k] + bias[h]  (rounded store)
    mma_gemm<<<dim3(H_ / 128, BN_ / 128), 128, TCSM>>>(
        Xr, WcombT, biascomb, gstar, BN_, H_, G_, 1);

    // s_proj[b,a] = sum_h str[b,h] * WsT[a,h]   (split-K x8, atomic)
    mma_gemm_splitk<<<dim3(A_ / 128, 1, 8), 128, TCSM>>>(
        str, WsT, sproj, B_, A_, H_, H_ / 8);

    // fused: e_pre + tanh + v-dot -> scores (epre never materialized)
    epre_scores_gemm<<<dim3(A_ / 128, BN_ / 128), 128, TCSM>>>(
        gstar, WhT, sproj, cov, W_c, v, scores);

    context_kernel<<<B_, 256>>>(scores, gstar, out);
}

// round 8
// speedup vs baseline: 1.6181x; 1.0659x over previous
#include <cuda_runtime.h>
#include <math.h>
#include <stdint.h>

// ===========================================================================
// img_attention via warp-level TF32 mma.sync (compute_103-safe)
//   c_img = softmax(v . tanh(Wh g* + Ws s + Wc cov)) @ g*
//   g*    = X @ (W_g @ W_gs) + (b_g @ W_gs + b_gs)      [algebraic fold]
// GEMMs: D[m,n] = sum_k A[m,k] * Bt[n,k]  (both K-major)
// R8: RNA rounding moved onto ldmatrix fragments (templated per-operand) —
//     X / W_g gmem rounding passes eliminated. bias_init folded into prep.
// ===========================================================================

#define B_   128
#define N_   49
#define G_   4096
#define H_   1024
#define A_   1024
#define BN_  (B_ * N_)   // 6272

__device__ float g_WcombT[H_ * G_];     // [1024,4096] (rounded)
__device__ float g_biascomb[H_];
__device__ float g_gstar[BN_ * H_];     // [6272,1024] (rounded)
__device__ float g_WgsT[H_ * G_];       // W_gs^T rounded [1024,4096]
__device__ float g_WhT[A_ * H_];        // rounded
__device__ float g_WsT[A_ * H_];        // rounded
__device__ float g_str[B_ * H_];        // s_t rounded
__device__ float g_sproj[B_ * A_];
__device__ float g_scores[BN_];

// ---------------------------------------------------------------------------
__device__ __forceinline__ uint32_t smem_u32(const void* p) {
    uint32_t a;
    asm("{ .reg .u64 t; cvta.to.shared.u64 t, %1; cvt.u32.u64 %0, t; }"
        : "=r"(a) : "l"(p));
    return a;
}
__device__ __forceinline__ float to_tf32(float x) {
    uint32_t u;
    asm("cvt.rna.tf32.f32 %0, %1;" : "=r"(u) : "f"(x));
    return __uint_as_float(u);
}
__device__ __forceinline__ uint32_t to_tf32_u(uint32_t x) {
    uint32_t u;
    asm("cvt.rna.tf32.f32 %0, %1;" : "=r"(u) : "f"(__uint_as_float(x)));
    return u;
}
__device__ __forceinline__ float tanh_approx(float x) {
    float y;
    asm("tanh.approx.f32 %0, %1;" : "=f"(y) : "f"(x));
    return y;
}
__device__ __forceinline__ void ldsm4(uint32_t* r, uint32_t addr) {
    asm volatile("ldmatrix.sync.aligned.m8n8.x4.shared.b16 {%0,%1,%2,%3}, [%4];"
                 : "=r"(r[0]), "=r"(r[1]), "=r"(r[2]), "=r"(r[3]) : "r"(addr));
}
__device__ __forceinline__ void mma_tf32(float* d, const uint32_t* a,
                                         const uint32_t* b) {
    asm volatile(
        "mma.sync.aligned.m16n8k8.row.col.f32.tf32.tf32.f32 "
        "{%0,%1,%2,%3}, {%4,%5,%6,%7}, {%8,%9}, {%0,%1,%2,%3};"
        : "+f"(d[0]), "+f"(d[1]), "+f"(d[2]), "+f"(d[3])
        : "r"(a[0]), "r"(a[1]), "r"(a[2]), "r"(a[3]), "r"(b[0]), "r"(b[1]));
}
#define CPA(dst, src) \
    asm volatile("cp.async.cg.shared.global [%0], [%1], 16;" \
                 :: "r"(dst), "l"(src) : "memory")
#define CPCOMMIT() asm volatile("cp.async.commit_group;" ::: "memory")
#define CPWAIT1()  asm volatile("cp.async.wait_group 1;" ::: "memory")
#define CPWAIT0()  asm volatile("cp.async.wait_group 0;" ::: "memory")

// ---------------------------------------------------------------------------
// GEMM machinery: 128x128 block, BK=32, 128 threads, 2x2 warps of 64x64.
// 3-stage cp.async ring: 3 x (16KB A + 16KB B) = 96KB.
// CVTA/CVTB: apply cvt.rna.tf32 to A/B fragments post-ldmatrix (compile-time).
// ---------------------------------------------------------------------------
#define STAGE_B 32768
#define TCSM (3 * STAGE_B)

#define GEMM_PROLOG()                                                         \
    extern __shared__ char smem[];                                            \
    const uint32_t sb = smem_u32(smem);                                       \
    const int tid = threadIdx.x;                                              \
    const int lane = tid & 31;                                                \
    const int wid = tid >> 5;                                                 \
    const int wr = wid >> 1;   /* 0..1 */                                     \
    const int wc = wid & 1;    /* 0..1 */                                     \
    const int srow = tid >> 3, sc4 = tid & 7;                                 \
    const uint32_t soff0 = (uint32_t)srow * 128 + ((sc4 ^ (srow & 7)) << 4);  \
    const int aRow = wr * 64 + ((lane >> 3) & 1) * 8 + (lane & 7);            \
    const int cbA = lane >> 4;                                                \
    const uint32_t aBase = (uint32_t)aRow * 128;                              \
    const int rmA = aRow & 7;                                                 \
    const int bRow = wc * 64 + (lane >> 4) * 8 + (lane & 7);                  \
    const int cbB = (lane >> 3) & 1;                                          \
    const uint32_t bBase = (uint32_t)bRow * 128;                              \
    const int rmB = bRow & 7;                                                 \
    float acc[4][8][4];                                                       \
    _Pragma("unroll") for (int i = 0; i < 4; i++)                             \
        _Pragma("unroll") for (int j = 0; j < 8; j++)                         \
            _Pragma("unroll") for (int q = 0; q < 4; q++) acc[i][j][q] = 0.f;

#define ISSUE_STAGE(sbase, k0) {                                              \
    _Pragma("unroll") for (int j = 0; j < 8; j++) {                           \
        CPA((sbase) + soff0 + j * 2048,         pA0 + (k0) + j * strideJ);    \
        CPA((sbase) + 16384 + soff0 + j * 2048, pB0 + (k0) + j * strideJ);    \
    }                                                                         \
    CPCOMMIT(); }

#define COMPUTE_CHUNK(As, Bs, CA, CB) {                                       \
    _Pragma("unroll") for (int kc = 0; kc < 4; kc++) {                        \
        uint32_t afr[4][4], bfr[8][2];                                        \
        _Pragma("unroll") for (int fm = 0; fm < 4; fm++) {                    \
            ldsm4(afr[fm],                                                    \
                  (As) + fm * 2048 + aBase + ((((kc * 2) + cbA) ^ rmA) << 4));\
            if (CA) {                                                         \
                _Pragma("unroll") for (int q = 0; q < 4; q++)                 \
                    afr[fm][q] = to_tf32_u(afr[fm][q]);                       \
            }                                                                 \
        }                                                                     \
        _Pragma("unroll") for (int p = 0; p < 4; p++) {                       \
            uint32_t t4[4];                                                   \
            ldsm4(t4,                                                         \
                  (Bs) + p * 2048 + bBase + ((((kc * 2) + cbB) ^ rmB) << 4)); \
            if (CB) {                                                         \
                _Pragma("unroll") for (int q = 0; q < 4; q++)                 \
                    t4[q] = to_tf32_u(t4[q]);                                 \
            }                                                                 \
            bfr[2*p][0]   = t4[0]; bfr[2*p][1]   = t4[1];                     \
            bfr[2*p+1][0] = t4[2]; bfr[2*p+1][1] = t4[3];                     \
        }                                                                     \
        _Pragma("unroll") for (int fm = 0; fm < 4; fm++)                      \
            _Pragma("unroll") for (int fn = 0; fn < 8; fn++)                  \
                mma_tf32(acc[fm][fn], afr[fm], bfr[fn]);                      \
    } }

// 3-stage pipeline; requires nch >= 2.
#define MAINLOOP(nch, CA, CB)                                                 \
    ISSUE_STAGE(sb, 0);                                                       \
    ISSUE_STAGE(sb + STAGE_B, 32);                                            \
    { int cs = 0, is = 2;                                                     \
    for (int c = 0; c < (nch); c++) {                                         \
        if (c == (nch) - 1) { CPWAIT0(); } else { CPWAIT1(); }                \
        __syncthreads();                                                      \
        if (c + 2 < (nch)) {                                                  \
            ISSUE_STAGE(sb + is * STAGE_B, (c + 2) * 32);                     \
            is = (is == 2) ? 0 : is + 1;                                      \
        }                                                                     \
        COMPUTE_CHUNK(sb + cs * STAGE_B, sb + cs * STAGE_B + 16384, CA, CB);  \
        cs = (cs == 2) ? 0 : cs + 1;                                          \
    } }

// ---------------------------------------------------------------------------
// Generic GEMM: D = A @ Bt^T (+ bias), optional TF32-rounded store.
// CVTA/CVTB: round raw fp32 operand fragments (for unrounded gmem inputs).
// ---------------------------------------------------------------------------
template <int CVTA, int CVTB>
__global__ __launch_bounds__(128, 2)
void mma_gemm(const float* __restrict__ A, const float* __restrict__ Bt,
              const float* __restrict__ bias, float* __restrict__ C,
              int M, int Nn, int K, int roundC)
{
    const int bm = blockIdx.y * 128;
    const int bn = blockIdx.x * 128;
    GEMM_PROLOG();
    const float* pA0 = A  + (size_t)(bm + srow) * K + sc4 * 4;
    const float* pB0 = Bt + (size_t)(bn + srow) * K + sc4 * 4;
    const size_t strideJ = (size_t)16 * K;
    const int nch = K >> 5;
    MAINLOOP(nch, CVTA, CVTB);

    const int gid = lane >> 2, tig = lane & 3;
    #pragma unroll
    for (int fm = 0; fm < 4; fm++) {
        const int row = bm + wr * 64 + fm * 16 + gid;
        #pragma unroll
        for (int fn = 0; fn < 8; fn++) {
            const int col = bn + wc * 64 + fn * 8 + tig * 2;
            float b0 = 0.f, b1 = 0.f;
            if (bias != nullptr) { b0 = bias[col]; b1 = bias[col + 1]; }
            float2 v01, v23;
            v01.x = acc[fm][fn][0] + b0; v01.y = acc[fm][fn][1] + b1;
            v23.x = acc[fm][fn][2] + b0; v23.y = acc[fm][fn][3] + b1;
            if (roundC) {
                v01.x = to_tf32(v01.x); v01.y = to_tf32(v01.y);
                v23.x = to_tf32(v23.x); v23.y = to_tf32(v23.y);
            }
            *(float2*)(C + (size_t)row * Nn + col) = v01;
            *(float2*)(C + (size_t)(row + 8) * Nn + col) = v23;
        }
    }
}

// ---------------------------------------------------------------------------
// Split-K GEMM for skinny M=128: C += A @ Bt^T over K slice (atomics).
// ---------------------------------------------------------------------------
__global__ __launch_bounds__(128, 2)
void mma_gemm_splitk(const float* __restrict__ A, const float* __restrict__ Bt,
                     float* __restrict__ C, int M, int Nn, int K, int klen)
{
    const int bm = blockIdx.y * 128;
    const int bn = blockIdx.x * 128;
    const int kbase = blockIdx.z * klen;
    GEMM_PROLOG();
    const float* pA0 = A  + (size_t)(bm + srow) * K + kbase + sc4 * 4;
    const float* pB0 = Bt + (size_t)(bn + srow) * K + kbase + sc4 * 4;
    const size_t strideJ = (size_t)16 * K;
    const int nch = klen >> 5;
    MAINLOOP(nch, 0, 0);

    const int gid = lane >> 2, tig = lane & 3;
    #pragma unroll
    for (int fm = 0; fm < 4; fm++) {
        const int row = bm + wr * 64 + fm * 16 + gid;
        #pragma unroll
        for (int fn = 0; fn < 8; fn++) {
            const int col = bn + wc * 64 + fn * 8 + tig * 2;
            atomicAdd(C + (size_t)row * Nn + col,       acc[fm][fn][0]);
            atomicAdd(C + (size_t)row * Nn + col + 1,   acc[fm][fn][1]);
            atomicAdd(C + (size_t)(row+8) * Nn + col,   acc[fm][fn][2]);
            atomicAdd(C + (size_t)(row+8) * Nn + col+1, acc[fm][fn][3]);
        }
    }
}

// ---------------------------------------------------------------------------
// Fused e_pre GEMM + scores epilogue. acc = gstar @ WhT^T (K=1024), then
// scores[row] += sum_col v[col]*tanh(acc + sproj[b,col] + cov[row]*Wc[col])
// ---------------------------------------------------------------------------
__global__ __launch_bounds__(128, 2)
void epre_scores_gemm(const float* __restrict__ A, const float* __restrict__ Bt,
                      const float* __restrict__ sproj,
                      const float* __restrict__ cov,
                      const float* __restrict__ Wc,
                      const float* __restrict__ v,
                      float* __restrict__ scores)
{
    const int bm = blockIdx.y * 128;
    const int bn = blockIdx.x * 128;
    GEMM_PROLOG();
    const float* pA0 = A  + (size_t)(bm + srow) * H_ + sc4 * 4;
    const float* pB0 = Bt + (size_t)(bn + srow) * H_ + sc4 * 4;
    const size_t strideJ = (size_t)16 * H_;
    MAINLOOP(H_ / 32, 0, 0);

    const int gid = lane >> 2, tig = lane & 3;
    float vv[16], wcv[16];
    #pragma unroll
    for (int fn = 0; fn < 8; fn++) {
        const int col = bn + wc * 64 + fn * 8 + tig * 2;
        vv[2*fn]   = v[col];      vv[2*fn+1]  = v[col + 1];
        wcv[2*fn]  = Wc[col];     wcv[2*fn+1] = Wc[col + 1];
    }
    #pragma unroll
    for (int fm = 0; fm < 4; fm++) {
        const int r0 = bm + wr * 64 + fm * 16 + gid;
        const int r1 = r0 + 8;
        const int b0i = r0 / N_, b1i = r1 / N_;
        const float c0 = cov[r0], c1 = cov[r1];
        const float* sp0 = sproj + (size_t)b0i * A_;
        const float* sp1 = sproj + (size_t)b1i * A_;
        float p0 = 0.f, p1 = 0.f;
        #pragma unroll
        for (int fn = 0; fn < 8; fn++) {
            const int col = bn + wc * 64 + fn * 8 + tig * 2;
            p0 += vv[2*fn]   * tanh_approx(acc[fm][fn][0] + sp0[col]     + c0 * wcv[2*fn]);
            p0 += vv[2*fn+1] * tanh_approx(acc[fm][fn][1] + sp0[col + 1] + c0 * wcv[2*fn+1]);
            p1 += vv[2*fn]   * tanh_approx(acc[fm][fn][2] + sp1[col]     + c1 * wcv[2*fn]);
            p1 += vv[2*fn+1] * tanh_approx(acc[fm][fn][3] + sp1[col + 1] + c1 * wcv[2*fn+1]);
        }
        p0 += __shfl_xor_sync(0xffffffffu, p0, 1);
        p0 += __shfl_xor_sync(0xffffffffu, p0, 2);
        p1 += __shfl_xor_sync(0xffffffffu, p1, 1);
        p1 += __shfl_xor_sync(0xffffffffu, p1, 2);
        if (tig == 0) {
            atomicAdd(scores + r0, p0);
            atomicAdd(scores + r1, p1);
        }
    }
}

// ---------------------------------------------------------------------------
// Batched prologue: rounded transposes, zero-fills, s_t rounding, bias init.
// ---------------------------------------------------------------------------
#define PREP_T1 4096
#define PREP_T2 (PREP_T1 + 1024)
#define PREP_T3 (PREP_T2 + 1024)
#define PREP_ZS (PREP_T3 + 25)
#define PREP_ZP (PREP_ZS + 512)
#define PREP_RS (PREP_ZP + 128)        // s_t: 128*1024/4/256
#define PREP_BI (PREP_RS + 4)          // bias init: 1024/256
#define PREP_END PREP_BI

__device__ __forceinline__ void do_transpose32r(
    const float* __restrict__ in, float* __restrict__ out,
    int R, int C, int tx, int ty)
{
    __shared__ float t[32][33];
    const int c0 = tx * 32, r0 = ty * 32;
    const int x = threadIdx.x & 31, y = (threadIdx.x >> 5);
    #pragma unroll
    for (int j = 0; j < 32; j += 8)
        t[y + j][x] = in[(size_t)(r0 + y + j) * C + c0 + x];
    __syncthreads();
    #pragma unroll
    for (int j = 0; j < 32; j += 8)
        out[(size_t)(c0 + y + j) * R + r0 + x] = to_tf32(t[x][y + j]);
}

__global__ __launch_bounds__(256) void prep_kernel(
    const float* __restrict__ W_gs, float* __restrict__ WgsT,
    const float* __restrict__ W_h,  float* __restrict__ WhT,
    const float* __restrict__ W_s,  float* __restrict__ WsT,
    const float* __restrict__ s_t,  float* __restrict__ str,
    const float* __restrict__ b_gs, float* __restrict__ biascomb,
    float* __restrict__ scores, float* __restrict__ sproj)
{
    const int bid = blockIdx.x;
    if (bid < PREP_T1) {
        do_transpose32r(W_gs, WgsT, G_, H_, bid & 31, bid >> 5);
    } else if (bid < PREP_T2) {
        const int b = bid - PREP_T1;
        do_transpose32r(W_h, WhT, H_, A_, b & 31, b >> 5);
    } else if (bid < PREP_T3) {
        const int b = bid - PREP_T2;
        do_transpose32r(W_s, WsT, H_, A_, b & 31, b >> 5);
    } else if (bid < PREP_ZS) {
        const int i = (bid - PREP_T3) * 256 + threadIdx.x;
        if (i < BN_) scores[i] = 0.f;
    } else if (bid < PREP_ZP) {
        const int i = (bid - PREP_ZS) * 256 + threadIdx.x;
        sproj[i] = 0.f;
    } else if (bid < PREP_RS) {
        const int i = (bid - PREP_ZP) * 256 + threadIdx.x;
        float4 x = *(const float4*)(s_t + (size_t)i * 4);
        x.x = to_tf32(x.x); x.y = to_tf32(x.y);
        x.z = to_tf32(x.z); x.w = to_tf32(x.w);
        *(float4*)(str + (size_t)i * 4) = x;
    } else {
        const int h = (bid - PREP_RS) * 256 + threadIdx.x;
        biascomb[h] = b_gs[h];
    }
}

__global__ void bias_acc_kernel(const float* __restrict__ b_g,
                                const float* __restrict__ W_gs,
                                float* __restrict__ bias) {
    int h = blockIdx.x * blockDim.x + threadIdx.x;
    int k0 = blockIdx.y * 256;
    float acc = 0.f;
    #pragma unroll 4
    for (int k = k0; k < k0 + 256; k++)
        acc += b_g[k] * W_gs[(size_t)k * H_ + h];
    atomicAdd(&bias[h], acc);
}

// softmax over N=49 + context c[b,h] = sum_n alpha[n] * gstar[b,n,h]
__global__ __launch_bounds__(256) void context_kernel(
    const float* __restrict__ scores, const float* __restrict__ gstar,
    float* __restrict__ out)
{
    const int b = blockIdx.x;
    __shared__ float alpha[N_];
    const int tid = threadIdx.x;

    if (tid == 0) {
        float m = -1e30f;
        #pragma unroll
        for (int n = 0; n < N_; n++) m = fmaxf(m, scores[b * N_ + n]);
        float s = 0.f;
        #pragma unroll
        for (int n = 0; n < N_; n++) {
            float e = expf(scores[b * N_ + n] - m);
            alpha[n] = e;
            s += e;
        }
        float inv = 1.f / s;
        #pragma unroll
        for (int n = 0; n < N_; n++) alpha[n] *= inv;
    }
    __syncthreads();

    const float* gb = gstar + (size_t)b * N_ * H_;
    for (int h = tid; h < H_; h += 256) {
        float acc = 0.f;
        #pragma unroll
        for (int n = 0; n < N_; n++)
            acc += alpha[n] * gb[(size_t)n * H_ + h];
        out[(size_t)b * H_ + h] = acc;
    }
}

// ---------------------------------------------------------------------------
extern "C" void kernel_launch(void* const* d_in, const int* in_sizes, int n_in,
                              void* d_out, int out_size) {
    const float* X    = (const float*)d_in[0];   // [6272,4096]
    const float* s_t  = (const float*)d_in[1];   // [128,1024]
    const float* cov  = (const float*)d_in[2];   // [6272]
    const float* W_g  = (const float*)d_in[3];   // [4096,4096]
    const float* b_g  = (const float*)d_in[4];   // [4096]
    const float* W_gs = (const float*)d_in[5];   // [4096,1024]
    const float* b_gs = (const float*)d_in[6];   // [1024]
    const float* W_h  = (const float*)d_in[7];   // [1024,1024]
    const float* W_s  = (const float*)d_in[8];   // [1024,1024]
    const float* W_c  = (const float*)d_in[9];   // [1024]
    const float* v    = (const float*)d_in[10];  // [1024]
    float* out = (float*)d_out;                  // [128,1024]

    float *WcombT, *biascomb, *gstar, *WgsT, *WhT, *WsT;
    float *str, *sproj, *scores;
    cudaGetSymbolAddress((void**)&WcombT,   g_WcombT);
    cudaGetSymbolAddress((void**)&biascomb, g_biascomb);
    cudaGetSymbolAddress((void**)&gstar,    g_gstar);
    cudaGetSymbolAddress((void**)&WgsT,     g_WgsT);
    cudaGetSymbolAddress((void**)&WhT,      g_WhT);
    cudaGetSymbolAddress((void**)&WsT,      g_WsT);
    cudaGetSymbolAddress((void**)&str,      g_str);
    cudaGetSymbolAddress((void**)&sproj,    g_sproj);
    cudaGetSymbolAddress((void**)&scores,   g_scores);

    cudaFuncSetAttribute(mma_gemm<0, 1>,
                         cudaFuncAttributeMaxDynamicSharedMemorySize, TCSM);
    cudaFuncSetAttribute(mma_gemm<1, 0>,
                         cudaFuncAttributeMaxDynamicSharedMemorySize, TCSM);
    cudaFuncSetAttribute(mma_gemm_splitk,
                         cudaFuncAttributeMaxDynamicSharedMemorySize, TCSM);
    cudaFuncSetAttribute(epre_scores_gemm,
                         cudaFuncAttributeMaxDynamicSharedMemorySize, TCSM);

    // prologue: rounded transposes, zero-fills, s_t rounding, bias init
    prep_kernel<<<PREP_END, 256>>>(W_gs, WgsT, W_h, WhT, W_s, WsT,
                                   s_t, str, b_gs, biascomb, scores, sproj);
    bias_acc_kernel<<<dim3(H_ / 256, G_ / 256), 256>>>(b_g, W_gs, biascomb);

    // WcombT[h,g] = sum_k WgsT[h,k] * W_g[g,k]  (B=W_g raw -> cvt frags)
    mma_gemm<0, 1><<<dim3(G_ / 128, H_ / 128), 128, TCSM>>>(
        WgsT, W_g, nullptr, WcombT, H_, G_, G_, 1);

    // g_star[m,h] = sum_k X[m,k] * WcombT[h,k] + bias  (A=X raw -> cvt frags)
    mma_gemm<1, 0><<<dim3(H_ / 128, BN_ / 128), 128, TCSM>>>(
        X, WcombT, biascomb, gstar, BN_, H_, G_, 1);

    // s_proj[b,a] = sum_h str[b,h] * WsT[a,h]   (split-K x8, atomic)
    mma_gemm_splitk<<<dim3(A_ / 128, 1, 8), 128, TCSM>>>(
        str, WsT, sproj, B_, A_, H_, H_ / 8);

    // fused: e_pre + tanh + v-dot -> scores (epre never materialized)
    epre_scores_gemm<<<dim3(A_ / 128, BN_ / 128), 128, TCSM>>>(
        gstar, WhT, sproj, cov, W_c, v, scores);

    context_kernel<<<B_, 256>>>(scores, gstar, out);
}